// round 3
// baseline (speedup 1.0000x reference)
#include <cuda_runtime.h>
#include <math.h>

// ---------------- problem dims ----------------
#define BB   128
#define SS   32
#define INF  512
#define HH   1024
#define OUTF 512
#define NN   16384
#define WW   128
#define CC   899
#define KL   (INF + WW + HH)   // 1664
#define RVSPLIT 256

// ---------------- persistent device state / scratch ----------------
__device__ float g_mem[NN * WW];          // 8 MB
__device__ float g_h[BB * HH];
__device__ float g_c[BB * HH];
__device__ float g_rw[(size_t)BB * NN];   // 8 MB (prev/next read weights)
__device__ float g_wwbuf[(size_t)BB * NN];// 8 MB (write weights)
__device__ float g_rv[BB * WW];
__device__ float g_gates[BB * 4 * HH];
__device__ float g_co[BB * CC];
__device__ float g_keys[2 * BB * WW];     // rows: [0..127]=rkey(b), [128..255]=wkey(b)
__device__ float g_er[BB * WW];
__device__ float g_ad[BB * WW];
__device__ float g_beta[2 * BB];
__device__ float g_gamma[2 * BB];
__device__ float g_invkey[2 * BB];
__device__ float g_invmem[NN];
__device__ float g_sim[(size_t)2 * BB * NN];        // 16 MB
__device__ float g_rvpart[(size_t)RVSPLIT * BB * WW]; // 16 MB

// ---------------- helpers ----------------
__device__ __forceinline__ float sigmoidf_(float x) { return 1.f / (1.f + expf(-x)); }
__device__ __forceinline__ float softplusf_(float x) { return x > 20.f ? x : log1pf(expf(x)); }

// packed f32x2 FMA: d += (a,a) * b   (sm_103a full-rate fp32 path)
__device__ __forceinline__ void ffma2(float2 &d, float a, float2 b) {
    float2 aa = make_float2(a, a);
    asm("fma.rn.f32x2 %0, %1, %2, %0;"
        : "+l"(reinterpret_cast<unsigned long long &>(d))
        : "l"(reinterpret_cast<unsigned long long &>(aa)),
          "l"(reinterpret_cast<unsigned long long &>(b)));
}

// ---------------- generic 64x64x16 tiled GEMM (256 thr, 4x4/thread) ----------------
// C[m,n] = sum_k A(m,k)*B(n,k); fetchers must bounds-guard; fe gets each element.
template <typename FA, typename FB, typename FE>
__device__ __forceinline__ void gemm_tile(int K, FA fa, FB fb, FE fe) {
    __shared__ float As[16][66];
    __shared__ float Bs[16][66];
    const int tid = threadIdx.x;
    const int m0 = blockIdx.y * 64;
    const int n0 = blockIdx.x * 64;
    const int ty = tid >> 4, tx = tid & 15;
    float2 acc[4][2];
#pragma unroll
    for (int i = 0; i < 4; i++) { acc[i][0] = make_float2(0.f, 0.f); acc[i][1] = make_float2(0.f, 0.f); }

    for (int k0 = 0; k0 < K; k0 += 16) {
#pragma unroll
        for (int i = 0; i < 4; i++) {
            int idx = tid + i * 256;          // 0..1023
            int kk = idx & 15, row = idx >> 4; // row 0..63 (k-fast for coalesced global)
            As[kk][row] = fa(m0 + row, k0 + kk);
        }
#pragma unroll
        for (int i = 0; i < 4; i++) {
            int idx = tid + i * 256;
            int kk = idx & 15, row = idx >> 4;
            Bs[kk][row] = fb(n0 + row, k0 + kk);
        }
        __syncthreads();
#pragma unroll
        for (int k = 0; k < 16; k++) {
            float a_[4];
#pragma unroll
            for (int i = 0; i < 4; i++) a_[i] = As[k][ty * 4 + i];
            float2 b0 = make_float2(Bs[k][tx * 4 + 0], Bs[k][tx * 4 + 1]);
            float2 b1 = make_float2(Bs[k][tx * 4 + 2], Bs[k][tx * 4 + 3]);
#pragma unroll
            for (int i = 0; i < 4; i++) { ffma2(acc[i][0], a_[i], b0); ffma2(acc[i][1], a_[i], b1); }
        }
        __syncthreads();
    }
#pragma unroll
    for (int i = 0; i < 4; i++) {
        fe(m0 + ty * 4 + i, n0 + tx * 4 + 0, acc[i][0].x);
        fe(m0 + ty * 4 + i, n0 + tx * 4 + 1, acc[i][0].y);
        fe(m0 + ty * 4 + i, n0 + tx * 4 + 2, acc[i][1].x);
        fe(m0 + ty * 4 + i, n0 + tx * 4 + 3, acc[i][1].y);
    }
}

// ---------------- kernels ----------------
__global__ void init_kernel(const float *__restrict__ memory) {
    int i = blockIdx.x * blockDim.x + threadIdx.x;   // 0..2097151
    g_mem[i] = memory[i];                            // NN*WW == 2097152
    g_rw[i] = 1.f / NN;                              // BB*NN == 2097152
    if (i < BB * HH) { g_h[i] = 0.f; g_c[i] = 0.f; }
    if (i < BB * WW) g_rv[i] = 0.f;
}

// gates = [x_t | rv | h] @ [Wih | Whh]^T + bih + bhh     (M=128, N=4096, K=1664)
__global__ void __launch_bounds__(256) gates_gemm(
    const float *__restrict__ x, const float *__restrict__ Wih, const float *__restrict__ Whh,
    const float *__restrict__ bih, const float *__restrict__ bhh, int t) {
    auto fa = [&](int m, int k) -> float {
        if (k < INF) return x[(size_t)m * SS * INF + (size_t)t * INF + k];
        if (k < INF + WW) return g_rv[m * WW + (k - INF)];
        return g_h[m * HH + (k - INF - WW)];
    };
    auto fb = [&](int n, int k) -> float {
        if (k < INF + WW) return Wih[(size_t)n * (INF + WW) + k];
        return Whh[(size_t)n * HH + (k - INF - WW)];
    };
    auto fe = [&](int m, int n, float v) { g_gates[m * 4 * HH + n] = v + bih[n] + bhh[n]; };
    gemm_tile(KL, fa, fb, fe);
}

__global__ void lstm_kernel() {
    int i = blockIdx.x * blockDim.x + threadIdx.x;
    if (i >= BB * HH) return;
    int b = i / HH, j = i - b * HH;
    const float *g = g_gates + b * 4 * HH;
    float gi = g[j], gf = g[HH + j], gg = g[2 * HH + j], go = g[3 * HH + j];
    float c = sigmoidf_(gf) * g_c[i] + sigmoidf_(gi) * tanhf(gg);
    float h = sigmoidf_(go) * tanhf(c);
    g_c[i] = c;
    g_h[i] = h;
}

// co = h @ Wout^T + bout    (M=128, N=899, K=1024)
__global__ void __launch_bounds__(256) co_gemm(const float *__restrict__ Wout, const float *__restrict__ bout) {
    auto fa = [&](int m, int k) { return g_h[m * HH + k]; };
    auto fb = [&](int n, int k) -> float { return (n < CC) ? Wout[(size_t)n * HH + k] : 0.f; };
    auto fe = [&](int m, int n, float v) { if (n < CC) g_co[m * CC + n] = v + bout[n]; };
    gemm_tile(HH, fa, fb, fe);
}

// all 8 head projections as one 516-column GEMM over co (K=899)
__global__ void __launch_bounds__(256) heads_gemm(
    const float *__restrict__ rkW, const float *__restrict__ rkb,
    const float *__restrict__ rbW, const float *__restrict__ rbb,
    const float *__restrict__ rgW, const float *__restrict__ rgb,
    const float *__restrict__ wkW, const float *__restrict__ wkb,
    const float *__restrict__ wbW, const float *__restrict__ wbb,
    const float *__restrict__ wgW, const float *__restrict__ wgb,
    const float *__restrict__ erW, const float *__restrict__ erb,
    const float *__restrict__ adW, const float *__restrict__ adb) {
    auto fa = [&](int m, int k) -> float { return (k < CC) ? g_co[m * CC + k] : 0.f; };
    auto fb = [&](int n, int k) -> float {
        if (k >= CC) return 0.f;
        if (n < 128) return rkW[n * CC + k];
        if (n < 256) return wkW[(n - 128) * CC + k];
        if (n < 384) return erW[(n - 256) * CC + k];
        if (n < 512) return adW[(n - 384) * CC + k];
        if (n == 512) return rbW[k];
        if (n == 513) return rgW[k];
        if (n == 514) return wbW[k];
        if (n == 515) return wgW[k];
        return 0.f;
    };
    auto fe = [&](int b, int n, float v) {
        if (n < 128)      g_keys[b * WW + n] = v + rkb[n];
        else if (n < 256) g_keys[(128 + b) * WW + (n - 128)] = v + wkb[n - 128];
        else if (n < 384) g_er[b * WW + (n - 256)] = sigmoidf_(v + erb[n - 256]);
        else if (n < 512) g_ad[b * WW + (n - 384)] = tanhf(v + adb[n - 384]);
        else if (n == 512) g_beta[b] = softplusf_(v + rbb[0]);
        else if (n == 513) g_gamma[b] = 1.f + softplusf_(v + rgb[0]);
        else if (n == 514) g_beta[128 + b] = softplusf_(v + wbb[0]);
        else if (n == 515) g_gamma[128 + b] = 1.f + softplusf_(v + wgb[0]);
    };
    gemm_tile(CC, fa, fb, fe);
}

// inverse L2 norms of memory rows (blocks 0..2047) and key rows (blocks 2048..2079)
__global__ void norm_kernel() {
    int warp = threadIdx.x >> 5, lane = threadIdx.x & 31;
    int bid = blockIdx.x;
    const float *p;
    float *dst;
    if (bid < NN / 8) {
        int row = bid * 8 + warp;
        p = g_mem + (size_t)row * WW;
        dst = g_invmem + row;
    } else {
        int r = (bid - NN / 8) * 8 + warp;
        if (r >= 2 * BB) return;
        p = g_keys + r * WW;
        dst = g_invkey + r;
    }
    float s = 0.f;
#pragma unroll
    for (int i = lane; i < WW; i += 32) { float v = p[i]; s = fmaf(v, v, s); }
#pragma unroll
    for (int o = 16; o; o >>= 1) s += __shfl_xor_sync(0xffffffffu, s, o);
    if (!lane) *dst = 1.f / fmaxf(sqrtf(s), 1e-12f);
}

// sim[r,n] = (key_r . mem_n) * invkey[r] * invmem[n]   (M=256, N=16384, K=128)
__global__ void __launch_bounds__(256) sim_gemm() {
    auto fa = [&](int r, int k) { return g_keys[r * WW + k]; };
    auto fb = [&](int n, int k) { return g_mem[(size_t)n * WW + k]; };
    auto fe = [&](int r, int n, float v) { g_sim[(size_t)r * NN + n] = v * g_invkey[r] * g_invmem[n]; };
    gemm_tile(WW, fa, fb, fe);
}

// per-row (head,b): softmax(beta*sim) then gamma-interp with prev weights
__global__ void softmax_kernel() {
    __shared__ float red[256];
    int r = blockIdx.x, head = r >> 7, b = r & 127;
    float beta = g_beta[r], gamma = g_gamma[r];
    const float *sim = g_sim + (size_t)r * NN;
    int tid = threadIdx.x;
    float mx = -1e30f;
    for (int n = tid; n < NN; n += 256) mx = fmaxf(mx, beta * sim[n]);
    red[tid] = mx; __syncthreads();
    for (int s = 128; s; s >>= 1) { if (tid < s) red[tid] = fmaxf(red[tid], red[tid + s]); __syncthreads(); }
    mx = red[0]; __syncthreads();
    float sum = 0.f;
    for (int n = tid; n < NN; n += 256) sum += expf(beta * sim[n] - mx);
    red[tid] = sum; __syncthreads();
    for (int s = 128; s; s >>= 1) { if (tid < s) red[tid] += red[tid + s]; __syncthreads(); }
    float inv = 1.f / red[0];
    float *dst = head ? (g_wwbuf + (size_t)b * NN) : (g_rw + (size_t)b * NN);
    const float om = 1.f - gamma;
    for (int n = tid; n < NN; n += 256) {
        float w = expf(beta * sim[n] - mx) * inv;
        float prev = head ? (1.f / NN) : dst[n];
        dst[n] = gamma * w + om * prev;
    }
}

// mem = mem*(1 - ww^T er) + ww^T ad   over a 64-row n-chunk per block
__global__ void __launch_bounds__(256) write_kernel() {
    __shared__ float wws[32][68];
    __shared__ float ers[32][132];
    __shared__ float ads[32][132];
    int tid = threadIdx.x;
    int n0 = blockIdx.x * 64;
    int nl0 = (tid >> 4) * 4;   // 0..60
    int w0 = (tid & 15) * 8;    // 0..120
    float2 eacc[4][4]; float2 aacc[4][4];
#pragma unroll
    for (int i = 0; i < 4; i++)
#pragma unroll
        for (int j = 0; j < 4; j++) { eacc[i][j] = make_float2(0.f, 0.f); aacc[i][j] = make_float2(0.f, 0.f); }

    for (int bt = 0; bt < BB; bt += 32) {
#pragma unroll
        for (int i = 0; i < 8; i++) {
            int idx = tid + i * 256;        // 0..2047
            int bl = idx >> 6, nl = idx & 63;
            wws[bl][nl] = g_wwbuf[(size_t)(bt + bl) * NN + n0 + nl];
        }
#pragma unroll
        for (int i = 0; i < 16; i++) {
            int idx = tid + i * 256;        // 0..4095
            int bl = idx >> 7, w = idx & 127;
            ers[bl][w] = g_er[(bt + bl) * WW + w];
            ads[bl][w] = g_ad[(bt + bl) * WW + w];
        }
        __syncthreads();
#pragma unroll 4
        for (int bl = 0; bl < 32; bl++) {
            float wv[4];
#pragma unroll
            for (int i = 0; i < 4; i++) wv[i] = wws[bl][nl0 + i];
            float2 ev[4], av[4];
#pragma unroll
            for (int j = 0; j < 4; j++) {
                ev[j] = make_float2(ers[bl][w0 + 2 * j], ers[bl][w0 + 2 * j + 1]);
                av[j] = make_float2(ads[bl][w0 + 2 * j], ads[bl][w0 + 2 * j + 1]);
            }
#pragma unroll
            for (int i = 0; i < 4; i++)
#pragma unroll
                for (int j = 0; j < 4; j++) { ffma2(eacc[i][j], wv[i], ev[j]); ffma2(aacc[i][j], wv[i], av[j]); }
        }
        __syncthreads();
    }
#pragma unroll
    for (int i = 0; i < 4; i++) {
        size_t base = (size_t)(n0 + nl0 + i) * WW + w0;
#pragma unroll
        for (int j = 0; j < 4; j++) {
            float m0v = g_mem[base + 2 * j], m1v = g_mem[base + 2 * j + 1];
            g_mem[base + 2 * j]     = m0v * (1.f - eacc[i][j].x) + aacc[i][j].x;
            g_mem[base + 2 * j + 1] = m1v * (1.f - eacc[i][j].y) + aacc[i][j].y;
        }
    }
}

// partial rv over a 64-row n-chunk: part[b,w] = sum_n rw[b,n]*mem[n,w]
__global__ void __launch_bounds__(256) rvpart_kernel() {
    __shared__ float rws[64][132];
    int tid = threadIdx.x;
    int n0 = blockIdx.x * 64;
#pragma unroll
    for (int i = 0; i < 32; i++) {
        int idx = tid + i * 256;   // 0..8191
        int b = idx >> 6, nl = idx & 63;
        rws[nl][b] = g_rw[(size_t)b * NN + n0 + nl];
    }
    __syncthreads();
    int b0 = (tid >> 4) * 8, w0 = (tid & 15) * 8;
    float2 acc[8][4];
#pragma unroll
    for (int i = 0; i < 8; i++)
#pragma unroll
        for (int j = 0; j < 4; j++) acc[i][j] = make_float2(0.f, 0.f);

    for (int nl = 0; nl < 64; nl++) {
        const float4 *mp = reinterpret_cast<const float4 *>(g_mem + (size_t)(n0 + nl) * WW + w0);
        float4 v0 = mp[0], v1 = mp[1];
        float2 mv[4] = { make_float2(v0.x, v0.y), make_float2(v0.z, v0.w),
                         make_float2(v1.x, v1.y), make_float2(v1.z, v1.w) };
        float rvv[8];
#pragma unroll
        for (int i = 0; i < 8; i++) rvv[i] = rws[nl][b0 + i];
#pragma unroll
        for (int i = 0; i < 8; i++)
#pragma unroll
            for (int j = 0; j < 4; j++) ffma2(acc[i][j], rvv[i], mv[j]);
    }
    float *dst = g_rvpart + (size_t)blockIdx.x * BB * WW;
#pragma unroll
    for (int i = 0; i < 8; i++)
#pragma unroll
        for (int j = 0; j < 4; j++) {
            dst[(b0 + i) * WW + w0 + 2 * j]     = acc[i][j].x;
            dst[(b0 + i) * WW + w0 + 2 * j + 1] = acc[i][j].y;
        }
}

__global__ void rvreduce_kernel() {
    int o = blockIdx.x * blockDim.x + threadIdx.x;
    if (o >= BB * WW) return;
    float s = 0.f;
    for (int ch = 0; ch < RVSPLIT; ch++) s += g_rvpart[(size_t)ch * BB * WW + o];
    g_rv[o] = s;
}

// out[b,t,:] = co[b,:512] @ pW^T + pb   (M=128, N=512, K=512)
__global__ void __launch_bounds__(256) out_gemm(const float *__restrict__ pW, const float *__restrict__ pb,
                                                float *__restrict__ out, int t) {
    auto fa = [&](int m, int k) { return g_co[m * CC + k]; };
    auto fb = [&](int n, int k) { return pW[(size_t)n * OUTF + k]; };
    auto fe = [&](int m, int n, float v) { out[(size_t)m * SS * OUTF + (size_t)t * OUTF + n] = v + pb[n]; };
    gemm_tile(OUTF, fa, fb, fe);
}

// ---------------- launch ----------------
extern "C" void kernel_launch(void *const *d_in, const int *in_sizes, int n_in,
                              void *d_out, int out_size) {
    const float *x      = (const float *)d_in[0];
    const float *memory = (const float *)d_in[1];
    const float *Wih    = (const float *)d_in[2];
    const float *Whh    = (const float *)d_in[3];
    const float *bih    = (const float *)d_in[4];
    const float *bhh    = (const float *)d_in[5];
    const float *Wout   = (const float *)d_in[6];
    const float *bout   = (const float *)d_in[7];
    const float *rkW    = (const float *)d_in[8];
    const float *rkb    = (const float *)d_in[9];
    const float *rbW    = (const float *)d_in[10];
    const float *rbb    = (const float *)d_in[11];
    const float *rgW    = (const float *)d_in[12];
    const float *rgb    = (const float *)d_in[13];
    const float *wkW    = (const float *)d_in[14];
    const float *wkb    = (const float *)d_in[15];
    const float *wbW    = (const float *)d_in[16];
    const float *wbb    = (const float *)d_in[17];
    const float *wgW    = (const float *)d_in[18];
    const float *wgb    = (const float *)d_in[19];
    const float *erW    = (const float *)d_in[20];
    const float *erb    = (const float *)d_in[21];
    const float *adW    = (const float *)d_in[22];
    const float *adb    = (const float *)d_in[23];
    const float *pW     = (const float *)d_in[24];
    const float *pb     = (const float *)d_in[25];
    float *out = (float *)d_out;

    init_kernel<<<8192, 256>>>(memory);
    for (int t = 0; t < SS; t++) {
        gates_gemm<<<dim3(64, 2), 256>>>(x, Wih, Whh, bih, bhh, t);
        lstm_kernel<<<512, 256>>>();
        co_gemm<<<dim3(15, 2), 256>>>(Wout, bout);
        heads_gemm<<<dim3(9, 2), 256>>>(rkW, rkb, rbW, rbb, rgW, rgb,
                                        wkW, wkb, wbW, wbb, wgW, wgb,
                                        erW, erb, adW, adb);
        norm_kernel<<<NN / 8 + 32, 256>>>();
        sim_gemm<<<dim3(256, 4), 256>>>();
        softmax_kernel<<<256, 256>>>();
        write_kernel<<<256, 256>>>();
        rvpart_kernel<<<256, 256>>>();
        rvreduce_kernel<<<64, 256>>>();
        out_gemm<<<dim3(8, 2), 256>>>(pW, pb, out, t);
    }
}

// round 5
// speedup vs baseline: 1.8556x; 1.8556x over previous
#include <cuda_runtime.h>
#include <math.h>

// ---------------- problem dims ----------------
#define BB   128
#define SS   32
#define INF  512
#define HH   1024
#define OUTF 512
#define NN   16384
#define WW   128
#define CC   899
#define KL   (INF + WW + HH)   // 1664
#define RVSPLIT 256
#define NHO  1028              // heads(516) + out(512) fused GEMM columns
#define NHOP 1088              // padded to 17*64

// ---------------- persistent device state / scratch ----------------
__device__ float g_mem[NN * WW];          // 8 MB
__device__ float g_h[BB * HH];
__device__ float g_c[BB * HH];
__device__ float g_rw[(size_t)BB * NN];   // 8 MB
__device__ float g_wwbuf[(size_t)BB * NN];// 8 MB
__device__ float g_rv[BB * WW];
__device__ float g_co[BB * CC];
__device__ float g_keys[2 * BB * WW];
__device__ float g_er[BB * WW];
__device__ float g_ad[BB * WW];
__device__ float g_beta[2 * BB];
__device__ float g_gamma[2 * BB];
__device__ float g_invmem[NN];
__device__ float g_sim[(size_t)2 * BB * NN];          // 16 MB
__device__ float g_rvpart[(size_t)RVSPLIT * BB * WW]; // 16 MB
// split-K partials
__device__ float g_gpart[2][BB * 4 * HH];             // 4 MB
__device__ float g_copart[8][BB * 960];               // 3.75 MB
__device__ float g_hopart[4][BB * NHOP];              // 2.2 MB

// ---------------- helpers ----------------
__device__ __forceinline__ float sigmoidf_(float x) { return 1.f / (1.f + __expf(-x)); }
__device__ __forceinline__ float softplusf_(float x) { return x > 20.f ? x : log1pf(__expf(x)); }

// packed f32x2 FMA: d += (a,a) * b   (sm_103a full-rate fp32 path)
__device__ __forceinline__ void ffma2(float2 &d, float a, float2 b) {
    float2 aa = make_float2(a, a);
    asm("fma.rn.f32x2 %0, %1, %2, %0;"
        : "+l"(reinterpret_cast<unsigned long long &>(d))
        : "l"(reinterpret_cast<unsigned long long &>(aa)),
          "l"(reinterpret_cast<unsigned long long &>(b)));
}

// ---------------- generic 64x64 tiled GEMM over k-range [kb,ke) ----------------
// C[m,n] = sum_k A(m,k)*B(n,k); fetchers must bounds-guard.
template <typename FA, typename FB, typename FE>
__device__ __forceinline__ void gemm_tile(int kb, int ke, FA fa, FB fb, FE fe) {
    __shared__ float As[16][66];
    __shared__ float Bs[16][66];
    const int tid = threadIdx.x;
    const int m0 = blockIdx.y * 64;
    const int n0 = blockIdx.x * 64;
    const int ty = tid >> 4, tx = tid & 15;
    float2 acc[4][2];
#pragma unroll
    for (int i = 0; i < 4; i++) { acc[i][0] = make_float2(0.f, 0.f); acc[i][1] = make_float2(0.f, 0.f); }

    for (int k0 = kb; k0 < ke; k0 += 16) {
#pragma unroll
        for (int i = 0; i < 4; i++) {
            int idx = tid + i * 256;
            int kk = idx & 15, row = idx >> 4;
            As[kk][row] = fa(m0 + row, k0 + kk);
        }
#pragma unroll
        for (int i = 0; i < 4; i++) {
            int idx = tid + i * 256;
            int kk = idx & 15, row = idx >> 4;
            Bs[kk][row] = fb(n0 + row, k0 + kk);
        }
        __syncthreads();
#pragma unroll
        for (int k = 0; k < 16; k++) {
            float a_[4];
#pragma unroll
            for (int i = 0; i < 4; i++) a_[i] = As[k][ty * 4 + i];
            float2 b0 = make_float2(Bs[k][tx * 4 + 0], Bs[k][tx * 4 + 1]);
            float2 b1 = make_float2(Bs[k][tx * 4 + 2], Bs[k][tx * 4 + 3]);
#pragma unroll
            for (int i = 0; i < 4; i++) { ffma2(acc[i][0], a_[i], b0); ffma2(acc[i][1], a_[i], b1); }
        }
        __syncthreads();
    }
#pragma unroll
    for (int i = 0; i < 4; i++) {
        fe(m0 + ty * 4 + i, n0 + tx * 4 + 0, acc[i][0].x);
        fe(m0 + ty * 4 + i, n0 + tx * 4 + 1, acc[i][0].y);
        fe(m0 + ty * 4 + i, n0 + tx * 4 + 2, acc[i][1].x);
        fe(m0 + ty * 4 + i, n0 + tx * 4 + 3, acc[i][1].y);
    }
}

// ---------------- kernels ----------------
__global__ void init_kernel(const float *__restrict__ memory) {
    int i = blockIdx.x * blockDim.x + threadIdx.x;
    g_mem[i] = memory[i];                            // NN*WW == 2097152
    g_rw[i] = 1.f / NN;                              // BB*NN == 2097152
    if (i < BB * HH) { g_h[i] = 0.f; g_c[i] = 0.f; }
    if (i < BB * WW) g_rv[i] = 0.f;
}

// one-time inverse L2 norms of initial memory rows (8 rows / block)
__global__ void initnorm_kernel() {
    int warp = threadIdx.x >> 5, lane = threadIdx.x & 31;
    int row = blockIdx.x * 8 + warp;
    const float *p = g_mem + (size_t)row * WW;
    float s = 0.f;
#pragma unroll
    for (int i = lane; i < WW; i += 32) { float v = p[i]; s = fmaf(v, v, s); }
#pragma unroll
    for (int o = 16; o; o >>= 1) s += __shfl_xor_sync(0xffffffffu, s, o);
    if (!lane) g_invmem[row] = 1.f / fmaxf(sqrtf(s), 1e-12f);
}

// gates partials: [x_t | rv | h] @ [Wih | Whh]^T   (M=128, N=4096, K split 2x832)
__global__ void __launch_bounds__(256) gates_gemm(
    const float *__restrict__ x, const float *__restrict__ Wih, const float *__restrict__ Whh, int t) {
    const int z = blockIdx.z;
    auto fa = [&](int m, int k) -> float {
        if (k < INF) return x[(size_t)m * SS * INF + (size_t)t * INF + k];
        if (k < INF + WW) return g_rv[m * WW + (k - INF)];
        return g_h[m * HH + (k - INF - WW)];
    };
    auto fb = [&](int n, int k) -> float {
        if (k < INF + WW) return Wih[(size_t)n * (INF + WW) + k];
        return Whh[(size_t)n * HH + (k - INF - WW)];
    };
    auto fe = [&](int m, int n, float v) { g_gpart[z][m * 4 * HH + n] = v; };
    gemm_tile(z * 832, (z + 1) * 832, fa, fb, fe);
}

__global__ void lstm_kernel(const float *__restrict__ bih, const float *__restrict__ bhh) {
    int i = blockIdx.x * blockDim.x + threadIdx.x;
    if (i >= BB * HH) return;
    int b = i / HH, j = i - b * HH;
    int base = b * 4 * HH;
    float gi = g_gpart[0][base + j] + g_gpart[1][base + j] + bih[j] + bhh[j];
    float gf = g_gpart[0][base + HH + j] + g_gpart[1][base + HH + j] + bih[HH + j] + bhh[HH + j];
    float gg = g_gpart[0][base + 2 * HH + j] + g_gpart[1][base + 2 * HH + j] + bih[2 * HH + j] + bhh[2 * HH + j];
    float go = g_gpart[0][base + 3 * HH + j] + g_gpart[1][base + 3 * HH + j] + bih[3 * HH + j] + bhh[3 * HH + j];
    float c = sigmoidf_(gf) * g_c[i] + sigmoidf_(gi) * tanhf(gg);
    float h = sigmoidf_(go) * tanhf(c);
    g_c[i] = c;
    g_h[i] = h;
}

// co partials: h @ Wout^T   (M=128, N=960 pad, K split 8x128)
__global__ void __launch_bounds__(256) co_gemm(const float *__restrict__ Wout) {
    const int z = blockIdx.z;
    auto fa = [&](int m, int k) { return g_h[m * HH + k]; };
    auto fb = [&](int n, int k) -> float { return (n < CC) ? Wout[(size_t)n * HH + k] : 0.f; };
    auto fe = [&](int m, int n, float v) { g_copart[z][m * 960 + n] = v; };
    gemm_tile(z * 128, (z + 1) * 128, fa, fb, fe);
}

__global__ void co_reduce(const float *__restrict__ bout) {
    int i = blockIdx.x * blockDim.x + threadIdx.x;
    if (i >= BB * CC) return;
    int b = i / CC, n = i - b * CC;
    float s = bout[n];
#pragma unroll
    for (int z = 0; z < 8; z++) s += g_copart[z][b * 960 + n];
    g_co[i] = s;
}

// fused heads(516 cols) + output proj(512 cols) partials over co (K split 4x240, guard k<899)
__global__ void __launch_bounds__(256) headsout_gemm(
    const float *__restrict__ rkW, const float *__restrict__ wkW,
    const float *__restrict__ erW, const float *__restrict__ adW,
    const float *__restrict__ rbW, const float *__restrict__ rgW,
    const float *__restrict__ wbW, const float *__restrict__ wgW,
    const float *__restrict__ pW) {
    const int z = blockIdx.z;
    auto fa = [&](int m, int k) -> float { return (k < CC) ? g_co[m * CC + k] : 0.f; };
    auto fb = [&](int n, int k) -> float {
        if (k >= CC) return 0.f;
        if (n < 128) return rkW[n * CC + k];
        if (n < 256) return wkW[(n - 128) * CC + k];
        if (n < 384) return erW[(n - 256) * CC + k];
        if (n < 512) return adW[(n - 384) * CC + k];
        if (n == 512) return rbW[k];
        if (n == 513) return rgW[k];
        if (n == 514) return wbW[k];
        if (n == 515) return wgW[k];
        if (n < NHO)  return (k < OUTF) ? pW[(size_t)(n - 516) * OUTF + k] : 0.f;
        return 0.f;
    };
    auto fe = [&](int m, int n, float v) { g_hopart[z][m * NHOP + n] = v; };
    gemm_tile(z * 240, (z + 1) * 240, fa, fb, fe);
}

// reduce 4 partials + activations; also writes output projection for step t
__global__ void headsout_epi(
    const float *__restrict__ rkb, const float *__restrict__ rbb, const float *__restrict__ rgb,
    const float *__restrict__ wkb, const float *__restrict__ wbb, const float *__restrict__ wgb,
    const float *__restrict__ erb, const float *__restrict__ adb,
    const float *__restrict__ pb, float *__restrict__ out, int t) {
    int i = blockIdx.x * blockDim.x + threadIdx.x;   // 0 .. 128*1028-1 exactly
    int b = i / NHO, n = i - b * NHO;
    float v = g_hopart[0][b * NHOP + n] + g_hopart[1][b * NHOP + n]
            + g_hopart[2][b * NHOP + n] + g_hopart[3][b * NHOP + n];
    if (n < 128)      g_keys[b * WW + n] = v + rkb[n];
    else if (n < 256) g_keys[(128 + b) * WW + (n - 128)] = v + wkb[n - 128];
    else if (n < 384) g_er[b * WW + (n - 256)] = sigmoidf_(v + erb[n - 256]);
    else if (n < 512) g_ad[b * WW + (n - 384)] = tanhf(v + adb[n - 384]);
    else if (n == 512) g_beta[b] = softplusf_(v + rbb[0]);
    else if (n == 513) g_gamma[b] = 1.f + softplusf_(v + rgb[0]);
    else if (n == 514) g_beta[128 + b] = softplusf_(v + wbb[0]);
    else if (n == 515) g_gamma[128 + b] = 1.f + softplusf_(v + wgb[0]);
    else { int o = n - 516; out[(size_t)b * SS * OUTF + (size_t)t * OUTF + o] = v + pb[o]; }
}

// sim[r,n] = (key_r . mem_n) * invkey[r] * invmem[n]; key invnorms computed in prologue
__global__ void __launch_bounds__(256) sim_gemm() {
    __shared__ float sh_ik[64];
    const int tid = threadIdx.x;
    const int r0 = blockIdx.y * 64;
    {   // 4 threads per key row compute inverse L2 norm
        int row = tid >> 2, part = tid & 3;
        const float *p = g_keys + (r0 + row) * WW;
        float s = 0.f;
#pragma unroll
        for (int j = 0; j < 32; j++) { float v = p[part + 4 * j]; s = fmaf(v, v, s); }
        s += __shfl_xor_sync(0xffffffffu, s, 1);
        s += __shfl_xor_sync(0xffffffffu, s, 2);
        if (!part) sh_ik[row] = 1.f / fmaxf(sqrtf(s), 1e-12f);
    }
    __syncthreads();
    auto fa = [&](int r, int k) { return g_keys[r * WW + k]; };
    auto fb = [&](int n, int k) { return g_mem[(size_t)n * WW + k]; };
    auto fe = [&](int r, int n, float v) { g_sim[(size_t)r * NN + n] = v * sh_ik[r - r0] * g_invmem[n]; };
    gemm_tile(0, WW, fa, fb, fe);
}

// per-row (head,b): softmax(beta*sim) then gamma-interp with prev weights
__global__ void softmax_kernel() {
    __shared__ float red[256];
    int r = blockIdx.x, head = r >> 7, b = r & 127;
    float beta = g_beta[r], gamma = g_gamma[r];
    const float *sim = g_sim + (size_t)r * NN;
    int tid = threadIdx.x;
    float mx = -1e30f;
    for (int n = tid; n < NN; n += 256) mx = fmaxf(mx, beta * sim[n]);
    red[tid] = mx; __syncthreads();
    for (int s = 128; s; s >>= 1) { if (tid < s) red[tid] = fmaxf(red[tid], red[tid + s]); __syncthreads(); }
    mx = red[0]; __syncthreads();
    float sum = 0.f;
    for (int n = tid; n < NN; n += 256) sum += __expf(beta * sim[n] - mx);
    red[tid] = sum; __syncthreads();
    for (int s = 128; s; s >>= 1) { if (tid < s) red[tid] += red[tid + s]; __syncthreads(); }
    float inv = 1.f / red[0];
    float *dst = head ? (g_wwbuf + (size_t)b * NN) : (g_rw + (size_t)b * NN);
    const float om = 1.f - gamma;
    for (int n = tid; n < NN; n += 256) {
        float w = __expf(beta * sim[n] - mx) * inv;
        float prev = head ? (1.f / NN) : dst[n];
        dst[n] = gamma * w + om * prev;
    }
}

// mem = mem*(1 - ww^T er) + ww^T ad over 64-row chunk; also emits new inverse row norms
__global__ void __launch_bounds__(256) write_kernel() {
    __shared__ float wws[32][68];
    __shared__ float ers[32][132];
    __shared__ float ads[32][132];
    int tid = threadIdx.x;
    int n0 = blockIdx.x * 64;
    int nl0 = (tid >> 4) * 4;   // 0..60
    int tx = tid & 15;
    int w0 = tx * 8;            // 0..120
    float2 eacc[4][4]; float2 aacc[4][4];
#pragma unroll
    for (int i = 0; i < 4; i++)
#pragma unroll
        for (int j = 0; j < 4; j++) { eacc[i][j] = make_float2(0.f, 0.f); aacc[i][j] = make_float2(0.f, 0.f); }

    for (int bt = 0; bt < BB; bt += 32) {
#pragma unroll
        for (int i = 0; i < 8; i++) {
            int idx = tid + i * 256;
            int bl = idx >> 6, nl = idx & 63;
            wws[bl][nl] = g_wwbuf[(size_t)(bt + bl) * NN + n0 + nl];
        }
#pragma unroll
        for (int i = 0; i < 16; i++) {
            int idx = tid + i * 256;
            int bl = idx >> 7, w = idx & 127;
            ers[bl][w] = g_er[(bt + bl) * WW + w];
            ads[bl][w] = g_ad[(bt + bl) * WW + w];
        }
        __syncthreads();
#pragma unroll 4
        for (int bl = 0; bl < 32; bl++) {
            float wv[4];
#pragma unroll
            for (int i = 0; i < 4; i++) wv[i] = wws[bl][nl0 + i];
            float2 ev[4], av[4];
#pragma unroll
            for (int j = 0; j < 4; j++) {
                ev[j] = make_float2(ers[bl][w0 + 2 * j], ers[bl][w0 + 2 * j + 1]);
                av[j] = make_float2(ads[bl][w0 + 2 * j], ads[bl][w0 + 2 * j + 1]);
            }
#pragma unroll
            for (int i = 0; i < 4; i++)
#pragma unroll
                for (int j = 0; j < 4; j++) { ffma2(eacc[i][j], wv[i], ev[j]); ffma2(aacc[i][j], wv[i], av[j]); }
        }
        __syncthreads();
    }
#pragma unroll
    for (int i = 0; i < 4; i++) {
        size_t base = (size_t)(n0 + nl0 + i) * WW + w0;
        float ss = 0.f;
#pragma unroll
        for (int j = 0; j < 4; j++) {
            float m0v = g_mem[base + 2 * j], m1v = g_mem[base + 2 * j + 1];
            float a0 = m0v * (1.f - eacc[i][j].x) + aacc[i][j].x;
            float a1 = m1v * (1.f - eacc[i][j].y) + aacc[i][j].y;
            g_mem[base + 2 * j]     = a0;
            g_mem[base + 2 * j + 1] = a1;
            ss = fmaf(a0, a0, fmaf(a1, a1, ss));
        }
        // reduce sumsq over the 16 w-threads (lane groups aligned to 16)
#pragma unroll
        for (int o = 1; o < 16; o <<= 1) ss += __shfl_xor_sync(0xffffffffu, ss, o);
        if (!tx) g_invmem[n0 + nl0 + i] = 1.f / fmaxf(sqrtf(ss), 1e-12f);
    }
}

// partial rv over a 64-row n-chunk: part[b,w] = sum_n rw[b,n]*mem[n,w]
__global__ void __launch_bounds__(256) rvpart_kernel() {
    __shared__ float rws[64][132];
    int tid = threadIdx.x;
    int n0 = blockIdx.x * 64;
#pragma unroll
    for (int i = 0; i < 32; i++) {
        int idx = tid + i * 256;
        int b = idx >> 6, nl = idx & 63;
        rws[nl][b] = g_rw[(size_t)b * NN + n0 + nl];
    }
    __syncthreads();
    int b0 = (tid >> 4) * 8, w0 = (tid & 15) * 8;
    float2 acc[8][4];
#pragma unroll
    for (int i = 0; i < 8; i++)
#pragma unroll
        for (int j = 0; j < 4; j++) acc[i][j] = make_float2(0.f, 0.f);

    for (int nl = 0; nl < 64; nl++) {
        const float4 *mp = reinterpret_cast<const float4 *>(g_mem + (size_t)(n0 + nl) * WW + w0);
        float4 v0 = mp[0], v1 = mp[1];
        float2 mv[4] = { make_float2(v0.x, v0.y), make_float2(v0.z, v0.w),
                         make_float2(v1.x, v1.y), make_float2(v1.z, v1.w) };
        float rvv[8];
#pragma unroll
        for (int i = 0; i < 8; i++) rvv[i] = rws[nl][b0 + i];
#pragma unroll
        for (int i = 0; i < 8; i++)
#pragma unroll
            for (int j = 0; j < 4; j++) ffma2(acc[i][j], rvv[i], mv[j]);
    }
    float *dst = g_rvpart + (size_t)blockIdx.x * BB * WW;
#pragma unroll
    for (int i = 0; i < 8; i++)
#pragma unroll
        for (int j = 0; j < 4; j++) {
            dst[(b0 + i) * WW + w0 + 2 * j]     = acc[i][j].x;
            dst[(b0 + i) * WW + w0 + 2 * j + 1] = acc[i][j].y;
        }
}

__global__ void rvreduce_kernel() {
    int o = blockIdx.x * blockDim.x + threadIdx.x;
    if (o >= BB * WW) return;
    float s = 0.f;
    for (int ch = 0; ch < RVSPLIT; ch++) s += g_rvpart[(size_t)ch * BB * WW + o];
    g_rv[o] = s;
}

// ---------------- launch ----------------
extern "C" void kernel_launch(void *const *d_in, const int *in_sizes, int n_in,
                              void *d_out, int out_size) {
    const float *x      = (const float *)d_in[0];
    const float *memory = (const float *)d_in[1];
    const float *Wih    = (const float *)d_in[2];
    const float *Whh    = (const float *)d_in[3];
    const float *bih    = (const float *)d_in[4];
    const float *bhh    = (const float *)d_in[5];
    const float *Wout   = (const float *)d_in[6];
    const float *bout   = (const float *)d_in[7];
    const float *rkW    = (const float *)d_in[8];
    const float *rkb    = (const float *)d_in[9];
    const float *rbW    = (const float *)d_in[10];
    const float *rbb    = (const float *)d_in[11];
    const float *rgW    = (const float *)d_in[12];
    const float *rgb    = (const float *)d_in[13];
    const float *wkW    = (const float *)d_in[14];
    const float *wkb    = (const float *)d_in[15];
    const float *wbW    = (const float *)d_in[16];
    const float *wbb    = (const float *)d_in[17];
    const float *wgW    = (const float *)d_in[18];
    const float *wgb    = (const float *)d_in[19];
    const float *erW    = (const float *)d_in[20];
    const float *erb    = (const float *)d_in[21];
    const float *adW    = (const float *)d_in[22];
    const float *adb    = (const float *)d_in[23];
    const float *pW     = (const float *)d_in[24];
    const float *pb     = (const float *)d_in[25];
    float *out = (float *)d_out;

    init_kernel<<<8192, 256>>>(memory);
    initnorm_kernel<<<NN / 8, 256>>>();
    for (int t = 0; t < SS; t++) {
        gates_gemm<<<dim3(64, 2, 2), 256>>>(x, Wih, Whh, t);
        lstm_kernel<<<512, 256>>>(bih, bhh);
        co_gemm<<<dim3(15, 2, 8), 256>>>(Wout);
        co_reduce<<<450, 256>>>(bout);
        headsout_gemm<<<dim3(17, 2, 4), 256>>>(rkW, wkW, erW, adW, rbW, rgW, wbW, wgW, pW);
        headsout_epi<<<514, 256>>>(rkb, rbb, rgb, wkb, wbb, wgb, erb, adb, pb, out, t);
        sim_gemm<<<dim3(256, 4), 256>>>();
        softmax_kernel<<<256, 256>>>();
        write_kernel<<<256, 256>>>();
        rvpart_kernel<<<256, 256>>>();
        rvreduce_kernel<<<64, 256>>>();
    }
}

// round 6
// speedup vs baseline: 2.0655x; 1.1132x over previous
#include <cuda_runtime.h>
#include <math.h>

// ---------------- problem dims ----------------
#define BB   128
#define SS   32
#define INF  512
#define HH   1024
#define OUTF 512
#define NN   16384
#define WW   128
#define CC   899
#define KL   (INF + WW + HH)   // 1664
#define RVSPLIT 256
#define NHO   1028             // heads(516) + out(512) fused GEMM columns
#define NHOP  1152             // padded to 9*128
#define GZ    8                // gates split-K
#define COZ   16               // co split-K
#define HOZ   15               // headsout split-K (15*64=960 >= 899)

// ---------------- persistent device state / scratch ----------------
__device__ float g_mem[NN * WW];          // 8 MB
__device__ float g_h[BB * HH];
__device__ float g_c[BB * HH];
__device__ float g_rw[(size_t)BB * NN];   // 8 MB
__device__ float g_wwbuf[(size_t)BB * NN];// 8 MB
__device__ float g_rv[BB * WW];
__device__ float g_co[BB * CC];
__device__ float g_keys[2 * BB * WW];
__device__ float g_er[BB * WW];
__device__ float g_ad[BB * WW];
__device__ float g_beta[2 * BB];
__device__ float g_gamma[2 * BB];
__device__ float g_invmem[NN];
__device__ float g_sim[(size_t)2 * BB * NN];          // 16 MB
__device__ float g_rvpart[(size_t)RVSPLIT * BB * WW]; // 16 MB
// split-K partials
__device__ float g_gpart[GZ][BB * 4 * HH];            // 16 MB
__device__ float g_copart[COZ][BB * 1024];            // 8 MB
__device__ float g_hopart[HOZ][BB * NHOP];            // 8.85 MB

// ---------------- helpers ----------------
__device__ __forceinline__ float sigmoidf_(float x) { return 1.f / (1.f + __expf(-x)); }
__device__ __forceinline__ float softplusf_(float x) { return x > 20.f ? x : log1pf(__expf(x)); }

// packed f32x2 FMA: d += (a,a) * b   (sm_103a full-rate fp32 path)
__device__ __forceinline__ void ffma2(float2 &d, float a, float2 b) {
    float2 aa = make_float2(a, a);
    asm("fma.rn.f32x2 %0, %1, %2, %0;"
        : "+l"(reinterpret_cast<unsigned long long &>(d))
        : "l"(reinterpret_cast<unsigned long long &>(aa)),
          "l"(reinterpret_cast<unsigned long long &>(b)));
}

// ---------------- 128x128 tiled GEMM, 8x8/thread, vectorized LDS ----------------
// C[m,n] = sum_{k in [kb,ke)} A(m,k)*B(n,k); fetchers must bounds-guard.
template <typename FA, typename FB, typename FE>
__device__ __forceinline__ void gemm_tile128(int kb, int ke, FA fa, FB fb, FE fe) {
    __shared__ float As[16][136];   // row stride 544B (16B multiple)
    __shared__ float Bs[16][136];
    const int tid = threadIdx.x;
    const int m0 = blockIdx.y * 128;
    const int n0 = blockIdx.x * 128;
    const int ty = tid >> 4, tx = tid & 15;
    float2 acc[8][4];
#pragma unroll
    for (int i = 0; i < 8; i++)
#pragma unroll
        for (int j = 0; j < 4; j++) acc[i][j] = make_float2(0.f, 0.f);

    for (int k0 = kb; k0 < ke; k0 += 16) {
#pragma unroll
        for (int i = 0; i < 8; i++) {
            int idx = tid + i * 256;              // 0..2047
            int kk = idx & 15, row = idx >> 4;    // k fast -> coalesced global
            As[kk][row] = fa(m0 + row, k0 + kk);
        }
#pragma unroll
        for (int i = 0; i < 8; i++) {
            int idx = tid + i * 256;
            int kk = idx & 15, row = idx >> 4;
            Bs[kk][row] = fb(n0 + row, k0 + kk);
        }
        __syncthreads();
#pragma unroll
        for (int k = 0; k < 16; k++) {
            float4 a0 = *reinterpret_cast<const float4 *>(&As[k][ty * 8]);
            float4 a1 = *reinterpret_cast<const float4 *>(&As[k][ty * 8 + 4]);
            float4 b0 = *reinterpret_cast<const float4 *>(&Bs[k][tx * 8]);
            float4 b1 = *reinterpret_cast<const float4 *>(&Bs[k][tx * 8 + 4]);
            float av[8] = {a0.x, a0.y, a0.z, a0.w, a1.x, a1.y, a1.z, a1.w};
            float2 bv[4] = {make_float2(b0.x, b0.y), make_float2(b0.z, b0.w),
                            make_float2(b1.x, b1.y), make_float2(b1.z, b1.w)};
#pragma unroll
            for (int i = 0; i < 8; i++)
#pragma unroll
                for (int j = 0; j < 4; j++) ffma2(acc[i][j], av[i], bv[j]);
        }
        __syncthreads();
    }
#pragma unroll
    for (int i = 0; i < 8; i++) {
        int m = m0 + ty * 8 + i;
#pragma unroll
        for (int j = 0; j < 4; j++) {
            fe(m, n0 + tx * 8 + 2 * j, acc[i][j].x);
            fe(m, n0 + tx * 8 + 2 * j + 1, acc[i][j].y);
        }
    }
}

// ---------------- kernels ----------------
__global__ void init_kernel(const float *__restrict__ memory) {
    int i = blockIdx.x * blockDim.x + threadIdx.x;
    g_mem[i] = memory[i];                            // NN*WW == 2097152
    g_rw[i] = 1.f / NN;                              // BB*NN == 2097152
    if (i < BB * HH) { g_h[i] = 0.f; g_c[i] = 0.f; }
    if (i < BB * WW) g_rv[i] = 0.f;
}

// one-time inverse L2 norms of initial memory rows (8 rows / block)
__global__ void initnorm_kernel() {
    int warp = threadIdx.x >> 5, lane = threadIdx.x & 31;
    int row = blockIdx.x * 8 + warp;
    const float *p = g_mem + (size_t)row * WW;
    float s = 0.f;
#pragma unroll
    for (int i = lane; i < WW; i += 32) { float v = p[i]; s = fmaf(v, v, s); }
#pragma unroll
    for (int o = 16; o; o >>= 1) s += __shfl_xor_sync(0xffffffffu, s, o);
    if (!lane) g_invmem[row] = 1.f / fmaxf(sqrtf(s), 1e-12f);
}

// gates partials: [x_t | rv | h] @ [Wih | Whh]^T   (M=128, N=4096, K split GZ x 208)
__global__ void __launch_bounds__(256, 2) gates_gemm(
    const float *__restrict__ x, const float *__restrict__ Wih, const float *__restrict__ Whh, int t) {
    const int z = blockIdx.z;
    auto fa = [&](int m, int k) -> float {
        if (k < INF) return x[(size_t)m * SS * INF + (size_t)t * INF + k];
        if (k < INF + WW) return g_rv[m * WW + (k - INF)];
        return g_h[m * HH + (k - INF - WW)];
    };
    auto fb = [&](int n, int k) -> float {
        if (k < INF + WW) return Wih[(size_t)n * (INF + WW) + k];
        return Whh[(size_t)n * HH + (k - INF - WW)];
    };
    auto fe = [&](int m, int n, float v) { g_gpart[z][m * 4 * HH + n] = v; };
    gemm_tile128(z * 208, (z + 1) * 208, fa, fb, fe);
}

__global__ void lstm_kernel(const float *__restrict__ bih, const float *__restrict__ bhh) {
    int i = blockIdx.x * blockDim.x + threadIdx.x;
    if (i >= BB * HH) return;
    int b = i / HH, j = i - b * HH;
    int base = b * 4 * HH;
    float gi = bih[j] + bhh[j];
    float gf = bih[HH + j] + bhh[HH + j];
    float gg = bih[2 * HH + j] + bhh[2 * HH + j];
    float go = bih[3 * HH + j] + bhh[3 * HH + j];
#pragma unroll
    for (int z = 0; z < GZ; z++) {
        gi += g_gpart[z][base + j];
        gf += g_gpart[z][base + HH + j];
        gg += g_gpart[z][base + 2 * HH + j];
        go += g_gpart[z][base + 3 * HH + j];
    }
    float c = sigmoidf_(gf) * g_c[i] + sigmoidf_(gi) * tanhf(gg);
    float h = sigmoidf_(go) * tanhf(c);
    g_c[i] = c;
    g_h[i] = h;
}

// co partials: h @ Wout^T   (M=128, N=1024 pad, K split COZ x 64)
__global__ void __launch_bounds__(256, 2) co_gemm(const float *__restrict__ Wout) {
    const int z = blockIdx.z;
    auto fa = [&](int m, int k) { return g_h[m * HH + k]; };
    auto fb = [&](int n, int k) -> float { return (n < CC) ? Wout[(size_t)n * HH + k] : 0.f; };
    auto fe = [&](int m, int n, float v) { g_copart[z][m * 1024 + n] = v; };
    gemm_tile128(z * 64, (z + 1) * 64, fa, fb, fe);
}

__global__ void co_reduce(const float *__restrict__ bout) {
    int i = blockIdx.x * blockDim.x + threadIdx.x;
    if (i >= BB * CC) return;
    int b = i / CC, n = i - b * CC;
    float s = bout[n];
#pragma unroll
    for (int z = 0; z < COZ; z++) s += g_copart[z][b * 1024 + n];
    g_co[i] = s;
}

// fused heads(516) + output proj(512) partials over co (K split HOZ x 64, guard k<899)
__global__ void __launch_bounds__(256, 2) headsout_gemm(
    const float *__restrict__ rkW, const float *__restrict__ wkW,
    const float *__restrict__ erW, const float *__restrict__ adW,
    const float *__restrict__ rbW, const float *__restrict__ rgW,
    const float *__restrict__ wbW, const float *__restrict__ wgW,
    const float *__restrict__ pW) {
    const int z = blockIdx.z;
    auto fa = [&](int m, int k) -> float { return (k < CC) ? g_co[m * CC + k] : 0.f; };
    auto fb = [&](int n, int k) -> float {
        if (k >= CC) return 0.f;
        if (n < 128) return rkW[n * CC + k];
        if (n < 256) return wkW[(n - 128) * CC + k];
        if (n < 384) return erW[(n - 256) * CC + k];
        if (n < 512) return adW[(n - 384) * CC + k];
        if (n == 512) return rbW[k];
        if (n == 513) return rgW[k];
        if (n == 514) return wbW[k];
        if (n == 515) return wgW[k];
        if (n < NHO)  return (k < OUTF) ? pW[(size_t)(n - 516) * OUTF + k] : 0.f;
        return 0.f;
    };
    auto fe = [&](int m, int n, float v) { g_hopart[z][m * NHOP + n] = v; };
    gemm_tile128(z * 64, (z + 1) * 64, fa, fb, fe);
}

// reduce HOZ partials + activations; also writes output projection for step t
__global__ void headsout_epi(
    const float *__restrict__ rkb, const float *__restrict__ rbb, const float *__restrict__ rgb,
    const float *__restrict__ wkb, const float *__restrict__ wbb, const float *__restrict__ wgb,
    const float *__restrict__ erb, const float *__restrict__ adb,
    const float *__restrict__ pb, float *__restrict__ out, int t) {
    int i = blockIdx.x * blockDim.x + threadIdx.x;   // 0 .. 128*1028-1 exactly
    int b = i / NHO, n = i - b * NHO;
    float v = 0.f;
#pragma unroll
    for (int z = 0; z < HOZ; z++) v += g_hopart[z][b * NHOP + n];
    if (n < 128)      g_keys[b * WW + n] = v + rkb[n];
    else if (n < 256) g_keys[(128 + b) * WW + (n - 128)] = v + wkb[n - 128];
    else if (n < 384) g_er[b * WW + (n - 256)] = sigmoidf_(v + erb[n - 256]);
    else if (n < 512) g_ad[b * WW + (n - 384)] = tanhf(v + adb[n - 384]);
    else if (n == 512) g_beta[b] = softplusf_(v + rbb[0]);
    else if (n == 513) g_gamma[b] = 1.f + softplusf_(v + rgb[0]);
    else if (n == 514) g_beta[128 + b] = softplusf_(v + wbb[0]);
    else if (n == 515) g_gamma[128 + b] = 1.f + softplusf_(v + wgb[0]);
    else { int o = n - 516; out[(size_t)b * SS * OUTF + (size_t)t * OUTF + o] = v + pb[o]; }
}

// sim[r,n] = (key_r . mem_n) * invkey[r] * invmem[n]; key invnorms in prologue
__global__ void __launch_bounds__(256, 2) sim_gemm() {
    __shared__ float sh_ik[128];
    const int tid = threadIdx.x;
    const int r0 = blockIdx.y * 128;
    {   // 2 threads per key row compute inverse L2 norm
        int row = tid >> 1, part = tid & 1;
        const float *p = g_keys + (r0 + row) * WW;
        float s = 0.f;
#pragma unroll
        for (int j = 0; j < 64; j++) { float v = p[part + 2 * j]; s = fmaf(v, v, s); }
        s += __shfl_xor_sync(0xffffffffu, s, 1);
        if (!part) sh_ik[row] = 1.f / fmaxf(sqrtf(s), 1e-12f);
    }
    auto fa = [&](int r, int k) { return g_keys[r * WW + k]; };
    auto fb = [&](int n, int k) { return g_mem[(size_t)n * WW + k]; };
    auto fe = [&](int r, int n, float v) { g_sim[(size_t)r * NN + n] = v * sh_ik[r - r0] * g_invmem[n]; };
    gemm_tile128(0, WW, fa, fb, fe);
}

// per-row (head,b): softmax(beta*sim) then gamma-interp with prev weights
__global__ void softmax_kernel() {
    __shared__ float red[256];
    int r = blockIdx.x, head = r >> 7, b = r & 127;
    float beta = g_beta[r], gamma = g_gamma[r];
    const float *sim = g_sim + (size_t)r * NN;
    int tid = threadIdx.x;
    float mx = -1e30f;
    for (int n = tid; n < NN; n += 256) mx = fmaxf(mx, beta * sim[n]);
    red[tid] = mx; __syncthreads();
    for (int s = 128; s; s >>= 1) { if (tid < s) red[tid] = fmaxf(red[tid], red[tid + s]); __syncthreads(); }
    mx = red[0]; __syncthreads();
    float sum = 0.f;
    for (int n = tid; n < NN; n += 256) sum += __expf(beta * sim[n] - mx);
    red[tid] = sum; __syncthreads();
    for (int s = 128; s; s >>= 1) { if (tid < s) red[tid] += red[tid + s]; __syncthreads(); }
    float inv = 1.f / red[0];
    float *dst = head ? (g_wwbuf + (size_t)b * NN) : (g_rw + (size_t)b * NN);
    const float om = 1.f - gamma;
    for (int n = tid; n < NN; n += 256) {
        float w = __expf(beta * sim[n] - mx) * inv;
        float prev = head ? (1.f / NN) : dst[n];
        dst[n] = gamma * w + om * prev;
    }
}

// mem = mem*(1 - ww^T er) + ww^T ad over 64-row chunk; emits new inverse row norms
__global__ void __launch_bounds__(256) write_kernel() {
    __shared__ float wws[32][68];
    __shared__ float ers[32][136];
    __shared__ float ads[32][136];
    int tid = threadIdx.x;
    int n0 = blockIdx.x * 64;
    int nl0 = (tid >> 4) * 4;   // 0..60
    int tx = tid & 15;
    int w0 = tx * 8;            // 0..120
    float2 eacc[4][4]; float2 aacc[4][4];
#pragma unroll
    for (int i = 0; i < 4; i++)
#pragma unroll
        for (int j = 0; j < 4; j++) { eacc[i][j] = make_float2(0.f, 0.f); aacc[i][j] = make_float2(0.f, 0.f); }

    for (int bt = 0; bt < BB; bt += 32) {
#pragma unroll
        for (int i = 0; i < 8; i++) {
            int idx = tid + i * 256;
            int bl = idx >> 6, nl = idx & 63;
            wws[bl][nl] = g_wwbuf[(size_t)(bt + bl) * NN + n0 + nl];
        }
#pragma unroll
        for (int i = 0; i < 16; i++) {
            int idx = tid + i * 256;
            int bl = idx >> 7, w = idx & 127;
            ers[bl][w] = g_er[(bt + bl) * WW + w];
            ads[bl][w] = g_ad[(bt + bl) * WW + w];
        }
        __syncthreads();
#pragma unroll 4
        for (int bl = 0; bl < 32; bl++) {
            float wv[4];
#pragma unroll
            for (int i = 0; i < 4; i++) wv[i] = wws[bl][nl0 + i];
            float4 e0 = *reinterpret_cast<const float4 *>(&ers[bl][w0]);
            float4 e1 = *reinterpret_cast<const float4 *>(&ers[bl][w0 + 4]);
            float4 d0 = *reinterpret_cast<const float4 *>(&ads[bl][w0]);
            float4 d1 = *reinterpret_cast<const float4 *>(&ads[bl][w0 + 4]);
            float2 ev[4] = {make_float2(e0.x, e0.y), make_float2(e0.z, e0.w),
                            make_float2(e1.x, e1.y), make_float2(e1.z, e1.w)};
            float2 av[4] = {make_float2(d0.x, d0.y), make_float2(d0.z, d0.w),
                            make_float2(d1.x, d1.y), make_float2(d1.z, d1.w)};
#pragma unroll
            for (int i = 0; i < 4; i++)
#pragma unroll
                for (int j = 0; j < 4; j++) { ffma2(eacc[i][j], wv[i], ev[j]); ffma2(aacc[i][j], wv[i], av[j]); }
        }
        __syncthreads();
    }
#pragma unroll
    for (int i = 0; i < 4; i++) {
        size_t base = (size_t)(n0 + nl0 + i) * WW + w0;
        float ss = 0.f;
#pragma unroll
        for (int j = 0; j < 4; j++) {
            float m0v = g_mem[base + 2 * j], m1v = g_mem[base + 2 * j + 1];
            float a0 = m0v * (1.f - eacc[i][j].x) + aacc[i][j].x;
            float a1 = m1v * (1.f - eacc[i][j].y) + aacc[i][j].y;
            g_mem[base + 2 * j]     = a0;
            g_mem[base + 2 * j + 1] = a1;
            ss = fmaf(a0, a0, fmaf(a1, a1, ss));
        }
#pragma unroll
        for (int o = 1; o < 16; o <<= 1) ss += __shfl_xor_sync(0xffffffffu, ss, o);
        if (!tx) g_invmem[n0 + nl0 + i] = 1.f / fmaxf(sqrtf(ss), 1e-12f);
    }
}

// partial rv over a 64-row n-chunk: part[b,w] = sum_n rw[b,n]*mem[n,w]
__global__ void __launch_bounds__(256) rvpart_kernel() {
    __shared__ float rws[64][136];
    int tid = threadIdx.x;
    int n0 = blockIdx.x * 64;
#pragma unroll
    for (int i = 0; i < 32; i++) {
        int idx = tid + i * 256;
        int b = idx >> 6, nl = idx & 63;
        rws[nl][b] = g_rw[(size_t)b * NN + n0 + nl];
    }
    __syncthreads();
    int b0 = (tid >> 4) * 8, w0 = (tid & 15) * 8;
    float2 acc[8][4];
#pragma unroll
    for (int i = 0; i < 8; i++)
#pragma unroll
        for (int j = 0; j < 4; j++) acc[i][j] = make_float2(0.f, 0.f);

    for (int nl = 0; nl < 64; nl++) {
        const float4 *mp = reinterpret_cast<const float4 *>(g_mem + (size_t)(n0 + nl) * WW + w0);
        float4 v0 = mp[0], v1 = mp[1];
        float2 mv[4] = {make_float2(v0.x, v0.y), make_float2(v0.z, v0.w),
                        make_float2(v1.x, v1.y), make_float2(v1.z, v1.w)};
        float4 r0 = *reinterpret_cast<const float4 *>(&rws[nl][b0]);
        float4 r1 = *reinterpret_cast<const float4 *>(&rws[nl][b0 + 4]);
        float rvv[8] = {r0.x, r0.y, r0.z, r0.w, r1.x, r1.y, r1.z, r1.w};
#pragma unroll
        for (int i = 0; i < 8; i++)
#pragma unroll
            for (int j = 0; j < 4; j++) ffma2(acc[i][j], rvv[i], mv[j]);
    }
    float *dst = g_rvpart + (size_t)blockIdx.x * BB * WW;
#pragma unroll
    for (int i = 0; i < 8; i++)
#pragma unroll
        for (int j = 0; j < 4; j++) {
            dst[(b0 + i) * WW + w0 + 2 * j]     = acc[i][j].x;
            dst[(b0 + i) * WW + w0 + 2 * j + 1] = acc[i][j].y;
        }
}

__global__ void rvreduce_kernel() {
    int o = blockIdx.x * blockDim.x + threadIdx.x;
    if (o >= BB * WW) return;
    float s = 0.f;
    for (int ch = 0; ch < RVSPLIT; ch++) s += g_rvpart[(size_t)ch * BB * WW + o];
    g_rv[o] = s;
}

// ---------------- launch ----------------
extern "C" void kernel_launch(void *const *d_in, const int *in_sizes, int n_in,
                              void *d_out, int out_size) {
    const float *x      = (const float *)d_in[0];
    const float *memory = (const float *)d_in[1];
    const float *Wih    = (const float *)d_in[2];
    const float *Whh    = (const float *)d_in[3];
    const float *bih    = (const float *)d_in[4];
    const float *bhh    = (const float *)d_in[5];
    const float *Wout   = (const float *)d_in[6];
    const float *bout   = (const float *)d_in[7];
    const float *rkW    = (const float *)d_in[8];
    const float *rkb    = (const float *)d_in[9];
    const float *rbW    = (const float *)d_in[10];
    const float *rbb    = (const float *)d_in[11];
    const float *rgW    = (const float *)d_in[12];
    const float *rgb    = (const float *)d_in[13];
    const float *wkW    = (const float *)d_in[14];
    const float *wkb    = (const float *)d_in[15];
    const float *wbW    = (const float *)d_in[16];
    const float *wbb    = (const float *)d_in[17];
    const float *wgW    = (const float *)d_in[18];
    const float *wgb    = (const float *)d_in[19];
    const float *erW    = (const float *)d_in[20];
    const float *erb    = (const float *)d_in[21];
    const float *adW    = (const float *)d_in[22];
    const float *adb    = (const float *)d_in[23];
    const float *pW     = (const float *)d_in[24];
    const float *pb     = (const float *)d_in[25];
    float *out = (float *)d_out;

    init_kernel<<<8192, 256>>>(memory);
    initnorm_kernel<<<NN / 8, 256>>>();
    for (int t = 0; t < SS; t++) {
        gates_gemm<<<dim3(32, 1, GZ), 256>>>(x, Wih, Whh, t);
        lstm_kernel<<<512, 256>>>(bih, bhh);
        co_gemm<<<dim3(8, 1, COZ), 256>>>(Wout);
        co_reduce<<<450, 256>>>(bout);
        headsout_gemm<<<dim3(9, 1, HOZ), 256>>>(rkW, wkW, erW, adW, rbW, rgW, wbW, wgW, pW);
        headsout_epi<<<514, 256>>>(rkb, rbb, rgb, wkb, wbb, wgb, erb, adb, pb, out, t);
        sim_gemm<<<dim3(128, 2), 256>>>();
        softmax_kernel<<<256, 256>>>();
        write_kernel<<<256, 256>>>();
        rvpart_kernel<<<256, 256>>>();
        rvreduce_kernel<<<64, 256>>>();
    }
}

// round 11
// speedup vs baseline: 2.6567x; 1.2862x over previous
#include <cuda_runtime.h>
#include <math.h>

// ---------------- problem dims ----------------
#define BB   128
#define SS   32
#define INF  512
#define HH   1024
#define OUTF 512
#define NN   16384
#define WW   128
#define CC   899
#define KL   (INF + WW + HH)   // 1664
#define RVSPLIT 256
#define NHO   1028             // heads(516) + out(512) fused GEMM columns
#define NHOP  1152             // padded
#define GZ    8                // gates split-K (chunks of 208)
#define COZ   8                // co split-K (chunks of 128)
#define HOZ   8                // headsout split-K (chunks of 128, guard k<899)

// ---------------- persistent device state / scratch ----------------
__device__ float g_mem[NN * WW];          // 8 MB
__device__ float g_h[BB * HH];
__device__ float g_c[BB * HH];
__device__ float g_rw[(size_t)BB * NN];   // 8 MB
__device__ float g_rv[BB * WW];
__device__ float g_co[BB * CC];
__device__ float g_keys[2 * BB * WW];
__device__ float g_er[BB * WW];
__device__ float g_ad[BB * WW];
__device__ float g_beta[2 * BB];
__device__ float g_gamma[2 * BB];
__device__ float g_invmem[NN];
__device__ float g_sim[(size_t)2 * BB * NN];          // 16 MB (beta-scaled sim)
__device__ float g_pmax[2 * BB * 128];                // per n-block partial max
__device__ float g_psum[2 * BB * 128];                // per n-block partial expsum
__device__ float g_mx[2 * BB];                        // row max
__device__ float g_inv[2 * BB];                       // row 1/sum
__device__ float g_rvpart[(size_t)RVSPLIT * BB * WW]; // 16 MB
// split-K partials
__device__ float g_gpart[GZ][BB * 4 * HH];            // 16 MB
__device__ float g_copart[COZ][BB * 1024];            // 4 MB
__device__ float g_hopart[HOZ][BB * NHOP];            // 4.7 MB

// ---------------- helpers ----------------
__device__ __forceinline__ float sigmoidf_(float x) { return 1.f / (1.f + __expf(-x)); }
__device__ __forceinline__ float softplusf_(float x) { return x > 20.f ? x : log1pf(__expf(x)); }

// packed f32x2 FMA: d += (a,a) * b
__device__ __forceinline__ void ffma2(float2 &d, float a, float2 b) {
    float2 aa = make_float2(a, a);
    asm("fma.rn.f32x2 %0, %1, %2, %0;"
        : "+l"(reinterpret_cast<unsigned long long &>(d))
        : "l"(reinterpret_cast<unsigned long long &>(aa)),
          "l"(reinterpret_cast<unsigned long long &>(b)));
}

// ---------------- 128x128 tiled GEMM, 8x8/thread, reg-prefetch pipeline ----------------
template <typename FA, typename FB, typename FE>
__device__ __forceinline__ void gemm_tile128(int kb, int ke, FA fa, FB fb, FE fe) {
    __shared__ float As[16][136];
    __shared__ float Bs[16][136];
    const int tid = threadIdx.x;
    const int m0 = blockIdx.y * 128;
    const int n0 = blockIdx.x * 128;
    const int ty = tid >> 4, tx = tid & 15;
    const int lkk = tid & 15, lr0 = tid >> 4;
    float2 acc[8][4];
#pragma unroll
    for (int i = 0; i < 8; i++)
#pragma unroll
        for (int j = 0; j < 4; j++) acc[i][j] = make_float2(0.f, 0.f);

    float ra[8], rb[8];
#pragma unroll
    for (int i = 0; i < 8; i++) {
        ra[i] = fa(m0 + lr0 + 16 * i, kb + lkk);
        rb[i] = fb(n0 + lr0 + 16 * i, kb + lkk);
    }
    for (int k0 = kb; k0 < ke; k0 += 16) {
#pragma unroll
        for (int i = 0; i < 8; i++) { As[lkk][lr0 + 16 * i] = ra[i]; Bs[lkk][lr0 + 16 * i] = rb[i]; }
        __syncthreads();
        if (k0 + 16 < ke) {
#pragma unroll
            for (int i = 0; i < 8; i++) {
                ra[i] = fa(m0 + lr0 + 16 * i, k0 + 16 + lkk);
                rb[i] = fb(n0 + lr0 + 16 * i, k0 + 16 + lkk);
            }
        }
#pragma unroll
        for (int k = 0; k < 16; k++) {
            float4 a0 = *reinterpret_cast<const float4 *>(&As[k][ty * 8]);
            float4 a1 = *reinterpret_cast<const float4 *>(&As[k][ty * 8 + 4]);
            float4 b0 = *reinterpret_cast<const float4 *>(&Bs[k][tx * 8]);
            float4 b1 = *reinterpret_cast<const float4 *>(&Bs[k][tx * 8 + 4]);
            float av[8] = {a0.x, a0.y, a0.z, a0.w, a1.x, a1.y, a1.z, a1.w};
            float2 bv[4] = {make_float2(b0.x, b0.y), make_float2(b0.z, b0.w),
                            make_float2(b1.x, b1.y), make_float2(b1.z, b1.w)};
#pragma unroll
            for (int i = 0; i < 8; i++)
#pragma unroll
                for (int j = 0; j < 4; j++) ffma2(acc[i][j], av[i], bv[j]);
        }
        __syncthreads();
    }
#pragma unroll
    for (int i = 0; i < 8; i++) {
        int m = m0 + ty * 8 + i;
#pragma unroll
        for (int j = 0; j < 4; j++) {
            fe(m, n0 + tx * 8 + 2 * j, acc[i][j].x);
            fe(m, n0 + tx * 8 + 2 * j + 1, acc[i][j].y);
        }
    }
}

// ---------------- 64x64 tiled GEMM, 4x4/thread, reg-prefetch (for short-K) ----------------
template <typename FA, typename FB, typename FE>
__device__ __forceinline__ void gemm_tile64(int kb, int ke, FA fa, FB fb, FE fe) {
    __shared__ float As[16][72];
    __shared__ float Bs[16][72];
    const int tid = threadIdx.x;
    const int m0 = blockIdx.y * 64;
    const int n0 = blockIdx.x * 64;
    const int ty = tid >> 4, tx = tid & 15;
    const int lkk = tid & 15, lr0 = tid >> 4;
    float2 acc[4][2];
#pragma unroll
    for (int i = 0; i < 4; i++) { acc[i][0] = make_float2(0.f, 0.f); acc[i][1] = make_float2(0.f, 0.f); }

    float ra[4], rb[4];
#pragma unroll
    for (int i = 0; i < 4; i++) {
        ra[i] = fa(m0 + lr0 + 16 * i, kb + lkk);
        rb[i] = fb(n0 + lr0 + 16 * i, kb + lkk);
    }
    for (int k0 = kb; k0 < ke; k0 += 16) {
#pragma unroll
        for (int i = 0; i < 4; i++) { As[lkk][lr0 + 16 * i] = ra[i]; Bs[lkk][lr0 + 16 * i] = rb[i]; }
        __syncthreads();
        if (k0 + 16 < ke) {
#pragma unroll
            for (int i = 0; i < 4; i++) {
                ra[i] = fa(m0 + lr0 + 16 * i, k0 + 16 + lkk);
                rb[i] = fb(n0 + lr0 + 16 * i, k0 + 16 + lkk);
            }
        }
#pragma unroll
        for (int k = 0; k < 16; k++) {
            float4 a0 = *reinterpret_cast<const float4 *>(&As[k][ty * 4]);
            float4 b0 = *reinterpret_cast<const float4 *>(&Bs[k][tx * 4]);
            float av[4] = {a0.x, a0.y, a0.z, a0.w};
            float2 bv[2] = {make_float2(b0.x, b0.y), make_float2(b0.z, b0.w)};
#pragma unroll
            for (int i = 0; i < 4; i++) { ffma2(acc[i][0], av[i], bv[0]); ffma2(acc[i][1], av[i], bv[1]); }
        }
        __syncthreads();
    }
#pragma unroll
    for (int i = 0; i < 4; i++) {
        int m = m0 + ty * 4 + i;
        fe(m, n0 + tx * 4 + 0, acc[i][0].x);
        fe(m, n0 + tx * 4 + 1, acc[i][0].y);
        fe(m, n0 + tx * 4 + 2, acc[i][1].x);
        fe(m, n0 + tx * 4 + 3, acc[i][1].y);
    }
}

// ---------------- kernels ----------------
__global__ void init_kernel(const float *__restrict__ memory) {
    int i = blockIdx.x * blockDim.x + threadIdx.x;
    g_mem[i] = memory[i];                            // NN*WW == 2097152
    g_rw[i] = 1.f / NN;                              // BB*NN == 2097152
    if (i < BB * HH) { g_h[i] = 0.f; g_c[i] = 0.f; }
    if (i < BB * WW) g_rv[i] = 0.f;
}

__global__ void initnorm_kernel() {
    int warp = threadIdx.x >> 5, lane = threadIdx.x & 31;
    int row = blockIdx.x * 8 + warp;
    const float *p = g_mem + (size_t)row * WW;
    float s = 0.f;
#pragma unroll
    for (int i = lane; i < WW; i += 32) { float v = p[i]; s = fmaf(v, v, s); }
#pragma unroll
    for (int o = 16; o; o >>= 1) s += __shfl_xor_sync(0xffffffffu, s, o);
    if (!lane) g_invmem[row] = 1.f / fmaxf(sqrtf(s), 1e-12f);
}

// gates partials: [x_t | rv | h] @ [Wih | Whh]^T   (M=128, N=4096, K split GZ x 208)
__global__ void __launch_bounds__(256, 2) gates_gemm(
    const float *__restrict__ x, const float *__restrict__ Wih, const float *__restrict__ Whh, int t) {
    const int z = blockIdx.z;
    auto fa = [&](int m, int k) -> float {
        if (k < INF) return x[(size_t)m * SS * INF + (size_t)t * INF + k];
        if (k < INF + WW) return g_rv[m * WW + (k - INF)];
        return g_h[m * HH + (k - INF - WW)];
    };
    auto fb = [&](int n, int k) -> float {
        if (k < INF + WW) return Wih[(size_t)n * (INF + WW) + k];
        return Whh[(size_t)n * HH + (k - INF - WW)];
    };
    auto fe = [&](int m, int n, float v) { g_gpart[z][m * 4 * HH + n] = v; };
    gemm_tile128(z * 208, (z + 1) * 208, fa, fb, fe);
}

__global__ void lstm_kernel(const float *__restrict__ bih, const float *__restrict__ bhh) {
    int i = blockIdx.x * blockDim.x + threadIdx.x;
    if (i >= BB * HH) return;
    int b = i / HH, j = i - b * HH;
    int base = b * 4 * HH;
    float gi = bih[j] + bhh[j];
    float gf = bih[HH + j] + bhh[HH + j];
    float gg = bih[2 * HH + j] + bhh[2 * HH + j];
    float go = bih[3 * HH + j] + bhh[3 * HH + j];
#pragma unroll
    for (int z = 0; z < GZ; z++) {
        gi += g_gpart[z][base + j];
        gf += g_gpart[z][base + HH + j];
        gg += g_gpart[z][base + 2 * HH + j];
        go += g_gpart[z][base + 3 * HH + j];
    }
    float c = sigmoidf_(gf) * g_c[i] + sigmoidf_(gi) * tanhf(gg);
    float h = sigmoidf_(go) * tanhf(c);
    g_c[i] = c;
    g_h[i] = h;
}

// co partials: h @ Wout^T   (M=128, N=1024 pad, K split COZ x 128), 64-tile
__global__ void __launch_bounds__(256, 4) co_gemm(const float *__restrict__ Wout) {
    const int z = blockIdx.z;
    auto fa = [&](int m, int k) { return g_h[m * HH + k]; };
    auto fb = [&](int n, int k) -> float { return (n < CC) ? Wout[(size_t)n * HH + k] : 0.f; };
    auto fe = [&](int m, int n, float v) { g_copart[z][m * 1024 + n] = v; };
    gemm_tile64(z * 128, (z + 1) * 128, fa, fb, fe);
}

__global__ void co_reduce(const float *__restrict__ bout) {
    int i = blockIdx.x * blockDim.x + threadIdx.x;
    if (i >= BB * CC) return;
    int b = i / CC, n = i - b * CC;
    float s = bout[n];
#pragma unroll
    for (int z = 0; z < COZ; z++) s += g_copart[z][b * 1024 + n];
    g_co[i] = s;
}

// fused heads(516) + output proj(512) partials over co (K split HOZ x 128, guard k<899), 64-tile
__global__ void __launch_bounds__(256, 4) headsout_gemm(
    const float *__restrict__ rkW, const float *__restrict__ wkW,
    const float *__restrict__ erW, const float *__restrict__ adW,
    const float *__restrict__ rbW, const float *__restrict__ rgW,
    const float *__restrict__ wbW, const float *__restrict__ wgW,
    const float *__restrict__ pW) {
    const int z = blockIdx.z;
    auto fa = [&](int m, int k) -> float { return (k < CC) ? g_co[m * CC + k] : 0.f; };
    auto fb = [&](int n, int k) -> float {
        if (k >= CC) return 0.f;
        if (n < 128) return rkW[n * CC + k];
        if (n < 256) return wkW[(n - 128) * CC + k];
        if (n < 384) return erW[(n - 256) * CC + k];
        if (n < 512) return adW[(n - 384) * CC + k];
        if (n == 512) return rbW[k];
        if (n == 513) return rgW[k];
        if (n == 514) return wbW[k];
        if (n == 515) return wgW[k];
        if (n < NHO)  return (k < OUTF) ? pW[(size_t)(n - 516) * OUTF + k] : 0.f;
        return 0.f;
    };
    auto fe = [&](int m, int n, float v) { g_hopart[z][m * NHOP + n] = v; };
    gemm_tile64(z * 128, (z + 1) * 128, fa, fb, fe);
}

// reduce HOZ partials + activations; writes output projection for step t
__global__ void headsout_epi(
    const float *__restrict__ rkb, const float *__restrict__ rbb, const float *__restrict__ rgb,
    const float *__restrict__ wkb, const float *__restrict__ wbb, const float *__restrict__ wgb,
    const float *__restrict__ erb, const float *__restrict__ adb,
    const float *__restrict__ pb, float *__restrict__ out, int t) {
    int i = blockIdx.x * blockDim.x + threadIdx.x;   // 0 .. 128*1028-1
    int b = i / NHO, n = i - b * NHO;
    float v = 0.f;
#pragma unroll
    for (int z = 0; z < HOZ; z++) v += g_hopart[z][b * NHOP + n];
    if (n < 128)      g_keys[b * WW + n] = v + rkb[n];
    else if (n < 256) g_keys[(128 + b) * WW + (n - 128)] = v + wkb[n - 128];
    else if (n < 384) g_er[b * WW + (n - 256)] = sigmoidf_(v + erb[n - 256]);
    else if (n < 512) g_ad[b * WW + (n - 384)] = tanhf(v + adb[n - 384]);
    else if (n == 512) g_beta[b] = softplusf_(v + rbb[0]);
    else if (n == 513) g_gamma[b] = 1.f + softplusf_(v + rgb[0]);
    else if (n == 514) g_beta[128 + b] = softplusf_(v + wbb[0]);
    else if (n == 515) g_gamma[128 + b] = 1.f + softplusf_(v + wgb[0]);
    else { int o = n - 516; out[(size_t)b * SS * OUTF + (size_t)t * OUTF + o] = v + pb[o]; }
}

// s[r,n] = beta[r]*(key_r . mem_n)*invkey[r]*invmem[n]; writes s and per-block
// online-softmax partials (max, expsum) per row.
__global__ void __launch_bounds__(256, 2) sim_gemm() {
    __shared__ float As[16][136];
    __shared__ float Bs[16][136];
    __shared__ float sh_bik[128];
    const int tid = threadIdx.x;
    const int r0 = blockIdx.y * 128;
    const int n0 = blockIdx.x * 128;
    const int nblk = blockIdx.x;
    const int ty = tid >> 4, tx = tid & 15;
    const int lkk = tid & 15, lr0 = tid >> 4;
    {   // 2 threads per key row: beta * inverse L2 norm
        int row = tid >> 1, part = tid & 1;
        const float *p = g_keys + (r0 + row) * WW;
        float s = 0.f;
#pragma unroll
        for (int j = 0; j < 64; j++) { float v = p[part + 2 * j]; s = fmaf(v, v, s); }
        s += __shfl_xor_sync(0xffffffffu, s, 1);
        if (!part) sh_bik[row] = g_beta[r0 + row] / fmaxf(sqrtf(s), 1e-12f);
    }
    float2 acc[8][4];
#pragma unroll
    for (int i = 0; i < 8; i++)
#pragma unroll
        for (int j = 0; j < 4; j++) acc[i][j] = make_float2(0.f, 0.f);

    float ra[8], rb[8];
#pragma unroll
    for (int i = 0; i < 8; i++) {
        ra[i] = g_keys[(r0 + lr0 + 16 * i) * WW + lkk];
        rb[i] = g_mem[(size_t)(n0 + lr0 + 16 * i) * WW + lkk];
    }
    for (int k0 = 0; k0 < WW; k0 += 16) {
#pragma unroll
        for (int i = 0; i < 8; i++) { As[lkk][lr0 + 16 * i] = ra[i]; Bs[lkk][lr0 + 16 * i] = rb[i]; }
        __syncthreads();
        if (k0 + 16 < WW) {
#pragma unroll
            for (int i = 0; i < 8; i++) {
                ra[i] = g_keys[(r0 + lr0 + 16 * i) * WW + k0 + 16 + lkk];
                rb[i] = g_mem[(size_t)(n0 + lr0 + 16 * i) * WW + k0 + 16 + lkk];
            }
        }
#pragma unroll
        for (int k = 0; k < 16; k++) {
            float4 a0 = *reinterpret_cast<const float4 *>(&As[k][ty * 8]);
            float4 a1 = *reinterpret_cast<const float4 *>(&As[k][ty * 8 + 4]);
            float4 b0 = *reinterpret_cast<const float4 *>(&Bs[k][tx * 8]);
            float4 b1 = *reinterpret_cast<const float4 *>(&Bs[k][tx * 8 + 4]);
            float av[8] = {a0.x, a0.y, a0.z, a0.w, a1.x, a1.y, a1.z, a1.w};
            float2 bv[4] = {make_float2(b0.x, b0.y), make_float2(b0.z, b0.w),
                            make_float2(b1.x, b1.y), make_float2(b1.z, b1.w)};
#pragma unroll
            for (int i = 0; i < 8; i++)
#pragma unroll
                for (int j = 0; j < 4; j++) ffma2(acc[i][j], av[i], bv[j]);
        }
        __syncthreads();
    }
    // epilogue: scale, store, per-row online-softmax partial over this n-block
    float im[8];
#pragma unroll
    for (int c = 0; c < 8; c++) im[c] = g_invmem[n0 + tx * 8 + c];
#pragma unroll
    for (int i = 0; i < 8; i++) {
        int rloc = ty * 8 + i;
        float bik = sh_bik[rloc];
        float vals[8];
#pragma unroll
        for (int j = 0; j < 4; j++) {
            vals[2 * j]     = acc[i][j].x * bik * im[2 * j];
            vals[2 * j + 1] = acc[i][j].y * bik * im[2 * j + 1];
        }
        float *dst = g_sim + (size_t)(r0 + rloc) * NN + n0 + tx * 8;
        *reinterpret_cast<float4 *>(dst)     = make_float4(vals[0], vals[1], vals[2], vals[3]);
        *reinterpret_cast<float4 *>(dst + 4) = make_float4(vals[4], vals[5], vals[6], vals[7]);
        float m = -1e30f;
#pragma unroll
        for (int c = 0; c < 8; c++) m = fmaxf(m, vals[c]);
        float s = 0.f;
#pragma unroll
        for (int c = 0; c < 8; c++) s += __expf(vals[c] - m);
#pragma unroll
        for (int off = 1; off < 16; off <<= 1) {
            float om = __shfl_xor_sync(0xffffffffu, m, off);
            float os = __shfl_xor_sync(0xffffffffu, s, off);
            float nm = fmaxf(m, om);
            s = s * __expf(m - nm) + os * __expf(om - nm);
            m = nm;
        }
        if (tx == 0) {
            int r = r0 + rloc;
            g_pmax[r * 128 + nblk] = m;
            g_psum[r * 128 + nblk] = s;
        }
    }
}

// combine the 128 per-block partials into per-row (max, 1/sum); warp per row
__global__ void softmax_finalize() {
    int r = blockIdx.x * 8 + (threadIdx.x >> 5);
    int lane = threadIdx.x & 31;
    float m = -1e30f, s = 0.f;
    for (int k = lane; k < 128; k += 32) {
        float pm = g_pmax[r * 128 + k], ps = g_psum[r * 128 + k];
        float nm = fmaxf(m, pm);
        s = s * __expf(m - nm) + ps * __expf(pm - nm);
        m = nm;
    }
#pragma unroll
    for (int off = 16; off; off >>= 1) {
        float om = __shfl_xor_sync(0xffffffffu, m, off);
        float os = __shfl_xor_sync(0xffffffffu, s, off);
        float nm = fmaxf(m, om);
        s = s * __expf(m - nm) + os * __expf(om - nm);
        m = nm;
    }
    if (!lane) { g_mx[r] = m; g_inv[r] = 1.f / s; }
}

// mem = mem*(1 - ww^T er) + ww^T ad; ww formed on the fly from sim (prev=uniform);
// emits new inverse row norms
__global__ void __launch_bounds__(256) write_kernel() {
    __shared__ float wws[32][68];
    __shared__ float ers[32][136];
    __shared__ float ads[32][136];
    __shared__ float shf1[128], shf2[128], shmx[128];
    int tid = threadIdx.x;
    if (tid < 128) {
        float gam = g_gamma[128 + tid];
        shf1[tid] = gam * g_inv[128 + tid];
        shf2[tid] = (1.f - gam) / NN;
        shmx[tid] = g_mx[128 + tid];
    }
    __syncthreads();
    int n0 = blockIdx.x * 64;
    int nl0 = (tid >> 4) * 4;
    int tx = tid & 15;
    int w0 = tx * 8;
    float2 eacc[4][4]; float2 aacc[4][4];
#pragma unroll
    for (int i = 0; i < 4; i++)
#pragma unroll
        for (int j = 0; j < 4; j++) { eacc[i][j] = make_float2(0.f, 0.f); aacc[i][j] = make_float2(0.f, 0.f); }

    for (int bt = 0; bt < BB; bt += 32) {
#pragma unroll
        for (int i = 0; i < 8; i++) {
            int idx = tid + i * 256;
            int bl = idx >> 6, nl = idx & 63;
            int b = bt + bl;
            float sv = g_sim[(size_t)(128 + b) * NN + n0 + nl];
            wws[bl][nl] = shf1[b] * __expf(sv - shmx[b]) + shf2[b];
        }
#pragma unroll
        for (int i = 0; i < 16; i++) {
            int idx = tid + i * 256;
            int bl = idx >> 7, w = idx & 127;
            ers[bl][w] = g_er[(bt + bl) * WW + w];
            ads[bl][w] = g_ad[(bt + bl) * WW + w];
        }
        __syncthreads();
#pragma unroll 4
        for (int bl = 0; bl < 32; bl++) {
            float wv[4];
#pragma unroll
            for (int i = 0; i < 4; i++) wv[i] = wws[bl][nl0 + i];
            float4 e0 = *reinterpret_cast<const float4 *>(&ers[bl][w0]);
            float4 e1 = *reinterpret_cast<const float4 *>(&ers[bl][w0 + 4]);
            float4 d0 = *reinterpret_cast<const float4 *>(&ads[bl][w0]);
            float4 d1 = *reinterpret_cast<const float4 *>(&ads[bl][w0 + 4]);
            float2 ev[4] = {make_float2(e0.x, e0.y), make_float2(e0.z, e0.w),
                            make_float2(e1.x, e1.y), make_float2(e1.z, e1.w)};
            float2 av[4] = {make_float2(d0.x, d0.y), make_float2(d0.z, d0.w),
                            make_float2(d1.x, d1.y), make_float2(d1.z, d1.w)};
#pragma unroll
            for (int i = 0; i < 4; i++)
#pragma unroll
                for (int j = 0; j < 4; j++) { ffma2(eacc[i][j], wv[i], ev[j]); ffma2(aacc[i][j], wv[i], av[j]); }
        }
        __syncthreads();
    }
#pragma unroll
    for (int i = 0; i < 4; i++) {
        size_t base = (size_t)(n0 + nl0 + i) * WW + w0;
        float ss = 0.f;
#pragma unroll
        for (int j = 0; j < 4; j++) {
            float m0v = g_mem[base + 2 * j], m1v = g_mem[base + 2 * j + 1];
            float a0 = m0v * (1.f - eacc[i][j].x) + aacc[i][j].x;
            float a1 = m1v * (1.f - eacc[i][j].y) + aacc[i][j].y;
            g_mem[base + 2 * j]     = a0;
            g_mem[base + 2 * j + 1] = a1;
            ss = fmaf(a0, a0, fmaf(a1, a1, ss));
        }
#pragma unroll
        for (int o = 1; o < 16; o <<= 1) ss += __shfl_xor_sync(0xffffffffu, ss, o);
        if (!tx) g_invmem[n0 + nl0 + i] = 1.f / fmaxf(sqrtf(ss), 1e-12f);
    }
}

// partial rv over a 64-row n-chunk; forms + persists new rw on the fly
__global__ void __launch_bounds__(256) rvpart_kernel() {
    __shared__ float rws[64][136];
    __shared__ float shf1[128], shf2[128], shmx[128];
    int tid = threadIdx.x;
    if (tid < 128) {
        float gam = g_gamma[tid];
        shf1[tid] = gam * g_inv[tid];
        shf2[tid] = 1.f - gam;
        shmx[tid] = g_mx[tid];
    }
    __syncthreads();
    int n0 = blockIdx.x * 64;
#pragma unroll
    for (int i = 0; i < 32; i++) {
        int idx = tid + i * 256;
        int b = idx >> 6, nl = idx & 63;
        size_t off = (size_t)b * NN + n0 + nl;
        float sv = g_sim[off];
        float w = shf1[b] * __expf(sv - shmx[b]) + shf2[b] * g_rw[off];
        g_rw[off] = w;
        rws[nl][b] = w;
    }
    __syncthreads();
    int b0 = (tid >> 4) * 8, w0 = (tid & 15) * 8;
    float2 acc[8][4];
#pragma unroll
    for (int i = 0; i < 8; i++)
#pragma unroll
        for (int j = 0; j < 4; j++) acc[i][j] = make_float2(0.f, 0.f);

    for (int nl = 0; nl < 64; nl++) {
        const float4 *mp = reinterpret_cast<const float4 *>(g_mem + (size_t)(n0 + nl) * WW + w0);
        float4 v0 = mp[0], v1 = mp[1];
        float2 mv[4] = {make_float2(v0.x, v0.y), make_float2(v0.z, v0.w),
                        make_float2(v1.x, v1.y), make_float2(v1.z, v1.w)};
        float4 r0 = *reinterpret_cast<const float4 *>(&rws[nl][b0]);
        float4 r1 = *reinterpret_cast<const float4 *>(&rws[nl][b0 + 4]);
        float rvv[8] = {r0.x, r0.y, r0.z, r0.w, r1.x, r1.y, r1.z, r1.w};
#pragma unroll
        for (int i = 0; i < 8; i++)
#pragma unroll
            for (int j = 0; j < 4; j++) ffma2(acc[i][j], rvv[i], mv[j]);
    }
    float *dst = g_rvpart + (size_t)blockIdx.x * BB * WW;
#pragma unroll
    for (int i = 0; i < 8; i++)
#pragma unroll
        for (int j = 0; j < 4; j++) {
            dst[(b0 + i) * WW + w0 + 2 * j]     = acc[i][j].x;
            dst[(b0 + i) * WW + w0 + 2 * j + 1] = acc[i][j].y;
        }
}

__global__ void rvreduce_kernel() {
    int o = blockIdx.x * blockDim.x + threadIdx.x;
    if (o >= BB * WW) return;
    float s = 0.f;
    for (int ch = 0; ch < RVSPLIT; ch++) s += g_rvpart[(size_t)ch * BB * WW + o];
    g_rv[o] = s;
}

// ---------------- launch ----------------
extern "C" void kernel_launch(void *const *d_in, const int *in_sizes, int n_in,
                              void *d_out, int out_size) {
    const float *x      = (const float *)d_in[0];
    const float *memory = (const float *)d_in[1];
    const float *Wih    = (const float *)d_in[2];
    const float *Whh    = (const float *)d_in[3];
    const float *bih    = (const float *)d_in[4];
    const float *bhh    = (const float *)d_in[5];
    const float *Wout   = (const float *)d_in[6];
    const float *bout   = (const float *)d_in[7];
    const float *rkW    = (const float *)d_in[8];
    const float *rkb    = (const float *)d_in[9];
    const float *rbW    = (const float *)d_in[10];
    const float *rbb    = (const float *)d_in[11];
    const float *rgW    = (const float *)d_in[12];
    const float *rgb    = (const float *)d_in[13];
    const float *wkW    = (const float *)d_in[14];
    const float *wkb    = (const float *)d_in[15];
    const float *wbW    = (const float *)d_in[16];
    const float *wbb    = (const float *)d_in[17];
    const float *wgW    = (const float *)d_in[18];
    const float *wgb    = (const float *)d_in[19];
    const float *erW    = (const float *)d_in[20];
    const float *erb    = (const float *)d_in[21];
    const float *adW    = (const float *)d_in[22];
    const float *adb    = (const float *)d_in[23];
    const float *pW     = (const float *)d_in[24];
    const float *pb     = (const float *)d_in[25];
    float *out = (float *)d_out;

    init_kernel<<<8192, 256>>>(memory);
    initnorm_kernel<<<NN / 8, 256>>>();
    for (int t = 0; t < SS; t++) {
        gates_gemm<<<dim3(32, 1, GZ), 256>>>(x, Wih, Whh, t);
        lstm_kernel<<<512, 256>>>(bih, bhh);
        co_gemm<<<dim3(16, 2, COZ), 256>>>(Wout);
        co_reduce<<<450, 256>>>(bout);
        headsout_gemm<<<dim3(17, 2, HOZ), 256>>>(rkW, wkW, erW, adW, rbW, rgW, wbW, wgW, pW);
        headsout_epi<<<514, 256>>>(rkb, rbb, rgb, wkb, wbb, wgb, erb, adb, pb, out, t);
        sim_gemm<<<dim3(128, 2), 256>>>();
        softmax_finalize<<<32, 256>>>();
        write_kernel<<<256, 256>>>();
        rvpart_kernel<<<256, 256>>>();
        rvreduce_kernel<<<64, 256>>>();
    }
}

// round 13
// speedup vs baseline: 2.8352x; 1.0672x over previous
#include <cuda_runtime.h>
#include <math.h>

// ---------------- problem dims ----------------
#define BB   128
#define SS   32
#define INF  512
#define HH   1024
#define OUTF 512
#define NN   16384
#define WW   128
#define CC   899
#define RVSPLIT 256
#define NHO   1028             // heads(516) + out(512) fused GEMM columns
#define NHOP  1152             // padded
#define GK    (WW + HH)        // per-step gates K = 1152
#define GZ    8                // gates split-K (chunks of 144)
#define COZ   8                // co split-K (chunks of 128)
#define HOZ   8                // headsout split-K (chunks of 128, guard k<899)

// ---------------- persistent device state / scratch ----------------
__device__ float g_mem[NN * WW];          // 8 MB
__device__ float g_h[BB * HH];
__device__ float g_c[BB * HH];
__device__ float g_rw[(size_t)BB * NN];   // 8 MB
__device__ float g_rv[BB * WW];
__device__ float g_co[BB * CC];
__device__ float g_keys[2 * BB * WW];
__device__ float g_er[BB * WW];
__device__ float g_ad[BB * WW];
__device__ float g_beta[2 * BB];
__device__ float g_gamma[2 * BB];
__device__ float g_invmem[NN];
__device__ float g_sim[(size_t)2 * BB * NN];          // 16 MB (beta-scaled sim)
__device__ float g_pmax[2 * BB * 128];
__device__ float g_psum[2 * BB * 128];
__device__ float g_mx[2 * BB];
__device__ float g_inv[2 * BB];
__device__ float g_rvpart[(size_t)RVSPLIT * BB * WW]; // 16 MB
__device__ float g_gx[(size_t)BB * SS * 4 * HH];      // 64 MB precomputed x-part of gates (+bias)
// split-K partials
__device__ float g_gpart[GZ][BB * 4 * HH];            // 16 MB
__device__ float g_copart[COZ][BB * 1024];            // 4 MB
__device__ float g_hopart[HOZ][BB * NHOP];            // 4.7 MB

// ---------------- helpers ----------------
__device__ __forceinline__ float sigmoidf_(float x) { return 1.f / (1.f + __expf(-x)); }
__device__ __forceinline__ float softplusf_(float x) { return x > 20.f ? x : log1pf(__expf(x)); }

// packed f32x2 FMA: d += (a,a) * b
__device__ __forceinline__ void ffma2(float2 &d, float a, float2 b) {
    float2 aa = make_float2(a, a);
    asm("fma.rn.f32x2 %0, %1, %2, %0;"
        : "+l"(reinterpret_cast<unsigned long long &>(d))
        : "l"(reinterpret_cast<unsigned long long &>(aa)),
          "l"(reinterpret_cast<unsigned long long &>(b)));
}

// ---------------- 128x128 tiled GEMM, 8x8/thread, reg-prefetch pipeline ----------------
template <typename FA, typename FB, typename FE>
__device__ __forceinline__ void gemm_tile128(int kb, int ke, FA fa, FB fb, FE fe) {
    __shared__ float As[16][136];
    __shared__ float Bs[16][136];
    const int tid = threadIdx.x;
    const int m0 = blockIdx.y * 128;
    const int n0 = blockIdx.x * 128;
    const int ty = tid >> 4, tx = tid & 15;
    const int lkk = tid & 15, lr0 = tid >> 4;
    float2 acc[8][4];
#pragma unroll
    for (int i = 0; i < 8; i++)
#pragma unroll
        for (int j = 0; j < 4; j++) acc[i][j] = make_float2(0.f, 0.f);

    float ra[8], rb[8];
#pragma unroll
    for (int i = 0; i < 8; i++) {
        ra[i] = fa(m0 + lr0 + 16 * i, kb + lkk);
        rb[i] = fb(n0 + lr0 + 16 * i, kb + lkk);
    }
    for (int k0 = kb; k0 < ke; k0 += 16) {
#pragma unroll
        for (int i = 0; i < 8; i++) { As[lkk][lr0 + 16 * i] = ra[i]; Bs[lkk][lr0 + 16 * i] = rb[i]; }
        __syncthreads();
        if (k0 + 16 < ke) {
#pragma unroll
            for (int i = 0; i < 8; i++) {
                ra[i] = fa(m0 + lr0 + 16 * i, k0 + 16 + lkk);
                rb[i] = fb(n0 + lr0 + 16 * i, k0 + 16 + lkk);
            }
        }
#pragma unroll
        for (int k = 0; k < 16; k++) {
            float4 a0 = *reinterpret_cast<const float4 *>(&As[k][ty * 8]);
            float4 a1 = *reinterpret_cast<const float4 *>(&As[k][ty * 8 + 4]);
            float4 b0 = *reinterpret_cast<const float4 *>(&Bs[k][tx * 8]);
            float4 b1 = *reinterpret_cast<const float4 *>(&Bs[k][tx * 8 + 4]);
            float av[8] = {a0.x, a0.y, a0.z, a0.w, a1.x, a1.y, a1.z, a1.w};
            float2 bv[4] = {make_float2(b0.x, b0.y), make_float2(b0.z, b0.w),
                            make_float2(b1.x, b1.y), make_float2(b1.z, b1.w)};
#pragma unroll
            for (int i = 0; i < 8; i++)
#pragma unroll
                for (int j = 0; j < 4; j++) ffma2(acc[i][j], av[i], bv[j]);
        }
        __syncthreads();
    }
#pragma unroll
    for (int i = 0; i < 8; i++) {
        int m = m0 + ty * 8 + i;
#pragma unroll
        for (int j = 0; j < 4; j++) {
            fe(m, n0 + tx * 8 + 2 * j, acc[i][j].x);
            fe(m, n0 + tx * 8 + 2 * j + 1, acc[i][j].y);
        }
    }
}

// ---------------- 64x64 tiled GEMM, 4x4/thread, reg-prefetch (for short-K) ----------------
template <typename FA, typename FB, typename FE>
__device__ __forceinline__ void gemm_tile64(int kb, int ke, FA fa, FB fb, FE fe) {
    __shared__ float As[16][72];
    __shared__ float Bs[16][72];
    const int tid = threadIdx.x;
    const int m0 = blockIdx.y * 64;
    const int n0 = blockIdx.x * 64;
    const int ty = tid >> 4, tx = tid & 15;
    const int lkk = tid & 15, lr0 = tid >> 4;
    float2 acc[4][2];
#pragma unroll
    for (int i = 0; i < 4; i++) { acc[i][0] = make_float2(0.f, 0.f); acc[i][1] = make_float2(0.f, 0.f); }

    float ra[4], rb[4];
#pragma unroll
    for (int i = 0; i < 4; i++) {
        ra[i] = fa(m0 + lr0 + 16 * i, kb + lkk);
        rb[i] = fb(n0 + lr0 + 16 * i, kb + lkk);
    }
    for (int k0 = kb; k0 < ke; k0 += 16) {
#pragma unroll
        for (int i = 0; i < 4; i++) { As[lkk][lr0 + 16 * i] = ra[i]; Bs[lkk][lr0 + 16 * i] = rb[i]; }
        __syncthreads();
        if (k0 + 16 < ke) {
#pragma unroll
            for (int i = 0; i < 4; i++) {
                ra[i] = fa(m0 + lr0 + 16 * i, k0 + 16 + lkk);
                rb[i] = fb(n0 + lr0 + 16 * i, k0 + 16 + lkk);
            }
        }
#pragma unroll
        for (int k = 0; k < 16; k++) {
            float4 a0 = *reinterpret_cast<const float4 *>(&As[k][ty * 4]);
            float4 b0 = *reinterpret_cast<const float4 *>(&Bs[k][tx * 4]);
            float av[4] = {a0.x, a0.y, a0.z, a0.w};
            float2 bv[2] = {make_float2(b0.x, b0.y), make_float2(b0.z, b0.w)};
#pragma unroll
            for (int i = 0; i < 4; i++) { ffma2(acc[i][0], av[i], bv[0]); ffma2(acc[i][1], av[i], bv[1]); }
        }
        __syncthreads();
    }
#pragma unroll
    for (int i = 0; i < 4; i++) {
        int m = m0 + ty * 4 + i;
        fe(m, n0 + tx * 4 + 0, acc[i][0].x);
        fe(m, n0 + tx * 4 + 1, acc[i][0].y);
        fe(m, n0 + tx * 4 + 2, acc[i][1].x);
        fe(m, n0 + tx * 4 + 3, acc[i][1].y);
    }
}

// ---------------- kernels ----------------
__global__ void init_kernel(const float *__restrict__ memory) {
    int i = blockIdx.x * blockDim.x + threadIdx.x;
    g_mem[i] = memory[i];                            // NN*WW == 2097152
    g_rw[i] = 1.f / NN;                              // BB*NN == 2097152
    if (i < BB * HH) { g_h[i] = 0.f; g_c[i] = 0.f; }
    if (i < BB * WW) g_rv[i] = 0.f;
}

__global__ void initnorm_kernel() {
    int warp = threadIdx.x >> 5, lane = threadIdx.x & 31;
    int row = blockIdx.x * 8 + warp;
    const float *p = g_mem + (size_t)row * WW;
    float s = 0.f;
#pragma unroll
    for (int i = lane; i < WW; i += 32) { float v = p[i]; s = fmaf(v, v, s); }
#pragma unroll
    for (int o = 16; o; o >>= 1) s += __shfl_xor_sync(0xffffffffu, s, o);
    if (!lane) g_invmem[row] = 1.f / fmaxf(sqrtf(s), 1e-12f);
}

// one-time: gx[(b*S+t), n] = x @ Wih_x^T + bih + bhh   (M=4096, N=4096, K=512)
__global__ void __launch_bounds__(256, 2) xgemm(
    const float *__restrict__ x, const float *__restrict__ Wih,
    const float *__restrict__ bih, const float *__restrict__ bhh) {
    auto fa = [&](int m, int k) { return x[(size_t)m * INF + k]; };
    auto fb = [&](int n, int k) { return Wih[(size_t)n * (INF + WW) + k]; };
    auto fe = [&](int m, int n, float v) { g_gx[(size_t)m * 4 * HH + n] = v + bih[n] + bhh[n]; };
    gemm_tile128(0, INF, fa, fb, fe);
}

// gates partials: [rv | h] @ [Wih_rv | Whh]^T   (M=128, N=4096, K=1152 split GZ x 144)
__global__ void __launch_bounds__(256, 2) gates_gemm(
    const float *__restrict__ Wih, const float *__restrict__ Whh) {
    const int z = blockIdx.z;
    auto fa = [&](int m, int k) -> float {
        if (k < WW) return g_rv[m * WW + k];
        return g_h[m * HH + (k - WW)];
    };
    auto fb = [&](int n, int k) -> float {
        if (k < WW) return Wih[(size_t)n * (INF + WW) + INF + k];
        return Whh[(size_t)n * HH + (k - WW)];
    };
    auto fe = [&](int m, int n, float v) { g_gpart[z][m * 4 * HH + n] = v; };
    gemm_tile128(z * 144, (z + 1) * 144, fa, fb, fe);
}

// vectorized reduce of gx + gpart -> LSTM pointwise (4 j's per thread)
__global__ void lstm_kernel(int t) {
    int idx = blockIdx.x * blockDim.x + threadIdx.x;   // 0..32767
    int b = idx >> 8;                 // HH/4 = 256 per batch
    int j4 = (idx & 255) * 4;
    size_t gxbase = ((size_t)(b * SS + t)) * 4 * HH;
    int pbase = b * 4 * HH;
    float4 gi = *reinterpret_cast<const float4 *>(&g_gx[gxbase + j4]);
    float4 gf = *reinterpret_cast<const float4 *>(&g_gx[gxbase + HH + j4]);
    float4 gg = *reinterpret_cast<const float4 *>(&g_gx[gxbase + 2 * HH + j4]);
    float4 go = *reinterpret_cast<const float4 *>(&g_gx[gxbase + 3 * HH + j4]);
#pragma unroll
    for (int z = 0; z < GZ; z++) {
        float4 a = *reinterpret_cast<const float4 *>(&g_gpart[z][pbase + j4]);
        float4 bq = *reinterpret_cast<const float4 *>(&g_gpart[z][pbase + HH + j4]);
        float4 cq = *reinterpret_cast<const float4 *>(&g_gpart[z][pbase + 2 * HH + j4]);
        float4 d = *reinterpret_cast<const float4 *>(&g_gpart[z][pbase + 3 * HH + j4]);
        gi.x += a.x; gi.y += a.y; gi.z += a.z; gi.w += a.w;
        gf.x += bq.x; gf.y += bq.y; gf.z += bq.z; gf.w += bq.w;
        gg.x += cq.x; gg.y += cq.y; gg.z += cq.z; gg.w += cq.w;
        go.x += d.x; go.y += d.y; go.z += d.z; go.w += d.w;
    }
    float4 c = *reinterpret_cast<const float4 *>(&g_c[b * HH + j4]);
    float4 nc, nh;
    nc.x = sigmoidf_(gf.x) * c.x + sigmoidf_(gi.x) * tanhf(gg.x);
    nc.y = sigmoidf_(gf.y) * c.y + sigmoidf_(gi.y) * tanhf(gg.y);
    nc.z = sigmoidf_(gf.z) * c.z + sigmoidf_(gi.z) * tanhf(gg.z);
    nc.w = sigmoidf_(gf.w) * c.w + sigmoidf_(gi.w) * tanhf(gg.w);
    nh.x = sigmoidf_(go.x) * tanhf(nc.x);
    nh.y = sigmoidf_(go.y) * tanhf(nc.y);
    nh.z = sigmoidf_(go.z) * tanhf(nc.z);
    nh.w = sigmoidf_(go.w) * tanhf(nc.w);
    *reinterpret_cast<float4 *>(&g_c[b * HH + j4]) = nc;
    *reinterpret_cast<float4 *>(&g_h[b * HH + j4]) = nh;
}

// co partials: h @ Wout^T   (M=128, N=1024 pad, K split COZ x 128), 64-tile
__global__ void __launch_bounds__(256, 4) co_gemm(const float *__restrict__ Wout) {
    const int z = blockIdx.z;
    auto fa = [&](int m, int k) { return g_h[m * HH + k]; };
    auto fb = [&](int n, int k) -> float { return (n < CC) ? Wout[(size_t)n * HH + k] : 0.f; };
    auto fe = [&](int m, int n, float v) { g_copart[z][m * 1024 + n] = v; };
    gemm_tile64(z * 128, (z + 1) * 128, fa, fb, fe);
}

__global__ void co_reduce(const float *__restrict__ bout) {
    int i = blockIdx.x * blockDim.x + threadIdx.x;
    if (i >= BB * CC) return;
    int b = i / CC, n = i - b * CC;
    float s = bout[n];
#pragma unroll
    for (int z = 0; z < COZ; z++) s += g_copart[z][b * 1024 + n];
    g_co[i] = s;
}

// fused heads(516) + output proj(512) partials over co (K split HOZ x 128, guard k<899), 64-tile
__global__ void __launch_bounds__(256, 4) headsout_gemm(
    const float *__restrict__ rkW, const float *__restrict__ wkW,
    const float *__restrict__ erW, const float *__restrict__ adW,
    const float *__restrict__ rbW, const float *__restrict__ rgW,
    const float *__restrict__ wbW, const float *__restrict__ wgW,
    const float *__restrict__ pW) {
    const int z = blockIdx.z;
    auto fa = [&](int m, int k) -> float { return (k < CC) ? g_co[m * CC + k] : 0.f; };
    auto fb = [&](int n, int k) -> float {
        if (k >= CC) return 0.f;
        if (n < 128) return rkW[n * CC + k];
        if (n < 256) return wkW[(n - 128) * CC + k];
        if (n < 384) return erW[(n - 256) * CC + k];
        if (n < 512) return adW[(n - 384) * CC + k];
        if (n == 512) return rbW[k];
        if (n == 513) return rgW[k];
        if (n == 514) return wbW[k];
        if (n == 515) return wgW[k];
        if (n < NHO)  return (k < OUTF) ? pW[(size_t)(n - 516) * OUTF + k] : 0.f;
        return 0.f;
    };
    auto fe = [&](int m, int n, float v) { g_hopart[z][m * NHOP + n] = v; };
    gemm_tile64(z * 128, (z + 1) * 128, fa, fb, fe);
}

// reduce HOZ partials + activations; writes output projection for step t
__global__ void headsout_epi(
    const float *__restrict__ rkb, const float *__restrict__ rbb, const float *__restrict__ rgb,
    const float *__restrict__ wkb, const float *__restrict__ wbb, const float *__restrict__ wgb,
    const float *__restrict__ erb, const float *__restrict__ adb,
    const float *__restrict__ pb, float *__restrict__ out, int t) {
    int i = blockIdx.x * blockDim.x + threadIdx.x;   // 0 .. 128*1028-1
    int b = i / NHO, n = i - b * NHO;
    float v = 0.f;
#pragma unroll
    for (int z = 0; z < HOZ; z++) v += g_hopart[z][b * NHOP + n];
    if (n < 128)      g_keys[b * WW + n] = v + rkb[n];
    else if (n < 256) g_keys[(128 + b) * WW + (n - 128)] = v + wkb[n - 128];
    else if (n < 384) g_er[b * WW + (n - 256)] = sigmoidf_(v + erb[n - 256]);
    else if (n < 512) g_ad[b * WW + (n - 384)] = tanhf(v + adb[n - 384]);
    else if (n == 512) g_beta[b] = softplusf_(v + rbb[0]);
    else if (n == 513) g_gamma[b] = 1.f + softplusf_(v + rgb[0]);
    else if (n == 514) g_beta[128 + b] = softplusf_(v + wbb[0]);
    else if (n == 515) g_gamma[128 + b] = 1.f + softplusf_(v + wgb[0]);
    else { int o = n - 516; out[(size_t)b * SS * OUTF + (size_t)t * OUTF + o] = v + pb[o]; }
}

// s[r,n] = beta[r]*(key_r . mem_n)*invkey[r]*invmem[n]; writes s + per-block softmax partials
__global__ void __launch_bounds__(256, 2) sim_gemm() {
    __shared__ float As[16][136];
    __shared__ float Bs[16][136];
    __shared__ float sh_bik[128];
    const int tid = threadIdx.x;
    const int r0 = blockIdx.y * 128;
    const int n0 = blockIdx.x * 128;
    const int nblk = blockIdx.x;
    const int ty = tid >> 4, tx = tid & 15;
    const int lkk = tid & 15, lr0 = tid >> 4;
    {
        int row = tid >> 1, part = tid & 1;
        const float *p = g_keys + (r0 + row) * WW;
        float s = 0.f;
#pragma unroll
        for (int j = 0; j < 64; j++) { float v = p[part + 2 * j]; s = fmaf(v, v, s); }
        s += __shfl_xor_sync(0xffffffffu, s, 1);
        if (!part) sh_bik[row] = g_beta[r0 + row] / fmaxf(sqrtf(s), 1e-12f);
    }
    float2 acc[8][4];
#pragma unroll
    for (int i = 0; i < 8; i++)
#pragma unroll
        for (int j = 0; j < 4; j++) acc[i][j] = make_float2(0.f, 0.f);

    float ra[8], rb[8];
#pragma unroll
    for (int i = 0; i < 8; i++) {
        ra[i] = g_keys[(r0 + lr0 + 16 * i) * WW + lkk];
        rb[i] = g_mem[(size_t)(n0 + lr0 + 16 * i) * WW + lkk];
    }
    for (int k0 = 0; k0 < WW; k0 += 16) {
#pragma unroll
        for (int i = 0; i < 8; i++) { As[lkk][lr0 + 16 * i] = ra[i]; Bs[lkk][lr0 + 16 * i] = rb[i]; }
        __syncthreads();
        if (k0 + 16 < WW) {
#pragma unroll
            for (int i = 0; i < 8; i++) {
                ra[i] = g_keys[(r0 + lr0 + 16 * i) * WW + k0 + 16 + lkk];
                rb[i] = g_mem[(size_t)(n0 + lr0 + 16 * i) * WW + k0 + 16 + lkk];
            }
        }
#pragma unroll
        for (int k = 0; k < 16; k++) {
            float4 a0 = *reinterpret_cast<const float4 *>(&As[k][ty * 8]);
            float4 a1 = *reinterpret_cast<const float4 *>(&As[k][ty * 8 + 4]);
            float4 b0 = *reinterpret_cast<const float4 *>(&Bs[k][tx * 8]);
            float4 b1 = *reinterpret_cast<const float4 *>(&Bs[k][tx * 8 + 4]);
            float av[8] = {a0.x, a0.y, a0.z, a0.w, a1.x, a1.y, a1.z, a1.w};
            float2 bv[4] = {make_float2(b0.x, b0.y), make_float2(b0.z, b0.w),
                            make_float2(b1.x, b1.y), make_float2(b1.z, b1.w)};
#pragma unroll
            for (int i = 0; i < 8; i++)
#pragma unroll
                for (int j = 0; j < 4; j++) ffma2(acc[i][j], av[i], bv[j]);
        }
        __syncthreads();
    }
    float im[8];
#pragma unroll
    for (int c = 0; c < 8; c++) im[c] = g_invmem[n0 + tx * 8 + c];
#pragma unroll
    for (int i = 0; i < 8; i++) {
        int rloc = ty * 8 + i;
        float bik = sh_bik[rloc];
        float vals[8];
#pragma unroll
        for (int j = 0; j < 4; j++) {
            vals[2 * j]     = acc[i][j].x * bik * im[2 * j];
            vals[2 * j + 1] = acc[i][j].y * bik * im[2 * j + 1];
        }
        float *dst = g_sim + (size_t)(r0 + rloc) * NN + n0 + tx * 8;
        *reinterpret_cast<float4 *>(dst)     = make_float4(vals[0], vals[1], vals[2], vals[3]);
        *reinterpret_cast<float4 *>(dst + 4) = make_float4(vals[4], vals[5], vals[6], vals[7]);
        float m = -1e30f;
#pragma unroll
        for (int c = 0; c < 8; c++) m = fmaxf(m, vals[c]);
        float s = 0.f;
#pragma unroll
        for (int c = 0; c < 8; c++) s += __expf(vals[c] - m);
#pragma unroll
        for (int off = 1; off < 16; off <<= 1) {
            float om = __shfl_xor_sync(0xffffffffu, m, off);
            float os = __shfl_xor_sync(0xffffffffu, s, off);
            float nm = fmaxf(m, om);
            s = s * __expf(m - nm) + os * __expf(om - nm);
            m = nm;
        }
        if (tx == 0) {
            int r = r0 + rloc;
            g_pmax[r * 128 + nblk] = m;
            g_psum[r * 128 + nblk] = s;
        }
    }
}

__global__ void softmax_finalize() {
    int r = blockIdx.x * 8 + (threadIdx.x >> 5);
    int lane = threadIdx.x & 31;
    float m = -1e30f, s = 0.f;
    for (int k = lane; k < 128; k += 32) {
        float pm = g_pmax[r * 128 + k], ps = g_psum[r * 128 + k];
        float nm = fmaxf(m, pm);
        s = s * __expf(m - nm) + ps * __expf(pm - nm);
        m = nm;
    }
#pragma unroll
    for (int off = 16; off; off >>= 1) {
        float om = __shfl_xor_sync(0xffffffffu, m, off);
        float os = __shfl_xor_sync(0xffffffffu, s, off);
        float nm = fmaxf(m, om);
        s = s * __expf(m - nm) + os * __expf(om - nm);
        m = nm;
    }
    if (!lane) { g_mx[r] = m; g_inv[r] = 1.f / s; }
}

// -------- fused memory write + rv partial over a 64-row n-chunk --------
// Phase A: ww from sim -> erase/add accumulation -> mem update (smem + gmem + invmem)
// Phase B: rw from sim (persisted) -> rv partials from smem-resident updated mem
// dynamic smem layout (floats):
//   [0, 8704)      rws [64][136]        (phase B)   / wws [32][68] (phase A, dead before rws)
//   [2176, 6528)   ers [32][136]        (phase A)
//   [6528, 10880)  ads [32][136]        (phase A)
//   [8704, 17152)  memu [64][132]       (written after phase A bt-loop; overlaps dead ads tail)
//   [17152, 17920) constants: f1w,f2w,mxw,f1r,f2r,mxr each [128]
#define SM_RWS   0
#define SM_ERS   2176
#define SM_ADS   6528
#define SM_MEMU  8704
#define SM_CONST 17152
#define WRV_SMEM_BYTES (17920 * 4)

__global__ void __launch_bounds__(256) writerv_kernel() {
    extern __shared__ float sm[];
    float *wws = sm;                 // [32][68] stride 68
    float *ers = sm + SM_ERS;        // [32][136]
    float *ads = sm + SM_ADS;        // [32][136]
    float *rws = sm + SM_RWS;        // [64][136]
    float *memu = sm + SM_MEMU;      // [64][132]
    float *f1w = sm + SM_CONST, *f2w = f1w + 128, *mxw = f2w + 128;
    float *f1r = mxw + 128, *f2r = f1r + 128, *mxr = f2r + 128;

    int tid = threadIdx.x;
    if (tid < 128) {
        float gw = g_gamma[128 + tid];
        f1w[tid] = gw * g_inv[128 + tid];
        f2w[tid] = (1.f - gw) / NN;
        mxw[tid] = g_mx[128 + tid];
        float gr = g_gamma[tid];
        f1r[tid] = gr * g_inv[tid];
        f2r[tid] = 1.f - gr;
        mxr[tid] = g_mx[tid];
    }
    __syncthreads();

    const int n0 = blockIdx.x * 64;
    const int nl0 = (tid >> 4) * 4;
    const int tx = tid & 15;
    const int w0 = tx * 8;

    // ---- Phase A: erase/add accumulation ----
    float2 eacc[4][4]; float2 aacc[4][4];
#pragma unroll
    for (int i = 0; i < 4; i++)
#pragma unroll
        for (int j = 0; j < 4; j++) { eacc[i][j] = make_float2(0.f, 0.f); aacc[i][j] = make_float2(0.f, 0.f); }

    for (int bt = 0; bt < BB; bt += 32) {
#pragma unroll
        for (int i = 0; i < 8; i++) {
            int idx = tid + i * 256;
            int bl = idx >> 6, nl = idx & 63;
            int b = bt + bl;
            float sv = g_sim[(size_t)(128 + b) * NN + n0 + nl];
            wws[bl * 68 + nl] = f1w[b] * __expf(sv - mxw[b]) + f2w[b];
        }
#pragma unroll
        for (int i = 0; i < 16; i++) {
            int idx = tid + i * 256;
            int bl = idx >> 7, w = idx & 127;
            ers[bl * 136 + w] = g_er[(bt + bl) * WW + w];
            ads[bl * 136 + w] = g_ad[(bt + bl) * WW + w];
        }
        __syncthreads();
#pragma unroll 4
        for (int bl = 0; bl < 32; bl++) {
            float wv[4];
#pragma unroll
            for (int i = 0; i < 4; i++) wv[i] = wws[bl * 68 + nl0 + i];
            float4 e0 = *reinterpret_cast<const float4 *>(&ers[bl * 136 + w0]);
            float4 e1 = *reinterpret_cast<const float4 *>(&ers[bl * 136 + w0 + 4]);
            float4 d0 = *reinterpret_cast<const float4 *>(&ads[bl * 136 + w0]);
            float4 d1 = *reinterpret_cast<const float4 *>(&ads[bl * 136 + w0 + 4]);
            float2 ev[4] = {make_float2(e0.x, e0.y), make_float2(e0.z, e0.w),
                            make_float2(e1.x, e1.y), make_float2(e1.z, e1.w)};
            float2 av[4] = {make_float2(d0.x, d0.y), make_float2(d0.z, d0.w),
                            make_float2(d1.x, d1.y), make_float2(d1.z, d1.w)};
#pragma unroll
            for (int i = 0; i < 4; i++)
#pragma unroll
                for (int j = 0; j < 4; j++) { ffma2(eacc[i][j], wv[i], ev[j]); ffma2(aacc[i][j], wv[i], av[j]); }
        }
        __syncthreads();
    }

    // ---- mem update: write gmem + smem(memu) + invmem; also form rw into rws ----
#pragma unroll
    for (int i = 0; i < 4; i++) {
        int nl = nl0 + i;
        size_t base = (size_t)(n0 + nl) * WW + w0;
        float ss = 0.f;
#pragma unroll
        for (int j = 0; j < 4; j++) {
            float m0v = g_mem[base + 2 * j], m1v = g_mem[base + 2 * j + 1];
            float a0 = m0v * (1.f - eacc[i][j].x) + aacc[i][j].x;
            float a1 = m1v * (1.f - eacc[i][j].y) + aacc[i][j].y;
            g_mem[base + 2 * j]     = a0;
            g_mem[base + 2 * j + 1] = a1;
            memu[nl * 132 + w0 + 2 * j]     = a0;
            memu[nl * 132 + w0 + 2 * j + 1] = a1;
            ss = fmaf(a0, a0, fmaf(a1, a1, ss));
        }
#pragma unroll
        for (int o = 1; o < 16; o <<= 1) ss += __shfl_xor_sync(0xffffffffu, ss, o);
        if (!tx) g_invmem[n0 + nl] = 1.f / fmaxf(sqrtf(ss), 1e-12f);
    }
#pragma unroll
    for (int i = 0; i < 32; i++) {
        int idx = tid + i * 256;
        int b = idx >> 6, nl = idx & 63;
        size_t off = (size_t)b * NN + n0 + nl;
        float sv = g_sim[off];
        float w = f1r[b] * __expf(sv - mxr[b]) + f2r[b] * g_rw[off];
        g_rw[off] = w;
        rws[nl * 136 + b] = w;
    }
    __syncthreads();

    // ---- Phase B: rv partials from updated smem rows ----
    int b0 = (tid >> 4) * 8, wq0 = (tid & 15) * 8;
    float2 acc[8][4];
#pragma unroll
    for (int i = 0; i < 8; i++)
#pragma unroll
        for (int j = 0; j < 4; j++) acc[i][j] = make_float2(0.f, 0.f);

    for (int nl = 0; nl < 64; nl++) {
        float4 v0 = *reinterpret_cast<const float4 *>(&memu[nl * 132 + wq0]);
        float4 v1 = *reinterpret_cast<const float4 *>(&memu[nl * 132 + wq0 + 4]);
        float2 mv[4] = {make_float2(v0.x, v0.y), make_float2(v0.z, v0.w),
                        make_float2(v1.x, v1.y), make_float2(v1.z, v1.w)};
        float4 r0 = *reinterpret_cast<const float4 *>(&rws[nl * 136 + b0]);
        float4 r1 = *reinterpret_cast<const float4 *>(&rws[nl * 136 + b0 + 4]);
        float rvv[8] = {r0.x, r0.y, r0.z, r0.w, r1.x, r1.y, r1.z, r1.w};
#pragma unroll
        for (int i = 0; i < 8; i++)
#pragma unroll
            for (int j = 0; j < 4; j++) ffma2(acc[i][j], rvv[i], mv[j]);
    }
    float *dst = g_rvpart + (size_t)blockIdx.x * BB * WW;
#pragma unroll
    for (int i = 0; i < 8; i++)
#pragma unroll
        for (int j = 0; j < 4; j++) {
            dst[(b0 + i) * WW + wq0 + 2 * j]     = acc[i][j].x;
            dst[(b0 + i) * WW + wq0 + 2 * j + 1] = acc[i][j].y;
        }
}

__global__ void rvreduce_kernel() {
    int o = blockIdx.x * blockDim.x + threadIdx.x;
    if (o >= BB * WW) return;
    float s = 0.f;
    for (int ch = 0; ch < RVSPLIT; ch++) s += g_rvpart[(size_t)ch * BB * WW + o];
    g_rv[o] = s;
}

// ---------------- launch ----------------
extern "C" void kernel_launch(void *const *d_in, const int *in_sizes, int n_in,
                              void *d_out, int out_size) {
    const float *x      = (const float *)d_in[0];
    const float *memory = (const float *)d_in[1];
    const float *Wih    = (const float *)d_in[2];
    const float *Whh    = (const float *)d_in[3];
    const float *bih    = (const float *)d_in[4];
    const float *bhh    = (const float *)d_in[5];
    const float *Wout   = (const float *)d_in[6];
    const float *bout   = (const float *)d_in[7];
    const float *rkW    = (const float *)d_in[8];
    const float *rkb    = (const float *)d_in[9];
    const float *rbW    = (const float *)d_in[10];
    const float *rbb    = (const float *)d_in[11];
    const float *rgW    = (const float *)d_in[12];
    const float *rgb    = (const float *)d_in[13];
    const float *wkW    = (const float *)d_in[14];
    const float *wkb    = (const float *)d_in[15];
    const float *wbW    = (const float *)d_in[16];
    const float *wbb    = (const float *)d_in[17];
    const float *wgW    = (const float *)d_in[18];
    const float *wgb    = (const float *)d_in[19];
    const float *erW    = (const float *)d_in[20];
    const float *erb    = (const float *)d_in[21];
    const float *adW    = (const float *)d_in[22];
    const float *adb    = (const float *)d_in[23];
    const float *pW     = (const float *)d_in[24];
    const float *pb     = (const float *)d_in[25];
    float *out = (float *)d_out;

    cudaFuncSetAttribute(writerv_kernel, cudaFuncAttributeMaxDynamicSharedMemorySize, WRV_SMEM_BYTES);

    init_kernel<<<8192, 256>>>(memory);
    initnorm_kernel<<<NN / 8, 256>>>();
    xgemm<<<dim3(32, 32), 256>>>(x, Wih, bih, bhh);
    for (int t = 0; t < SS; t++) {
        gates_gemm<<<dim3(32, 1, GZ), 256>>>(Wih, Whh);
        lstm_kernel<<<128, 256>>>(t);
        co_gemm<<<dim3(16, 2, COZ), 256>>>(Wout);
        co_reduce<<<450, 256>>>(bout);
        headsout_gemm<<<dim3(17, 2, HOZ), 256>>>(rkW, wkW, erW, adW, rbW, rgW, wbW, wgW, pW);
        headsout_epi<<<514, 256>>>(rkb, rbb, rgb, wkb, wbb, wgb, erb, adb, pb, out, t);
        sim_gemm<<<dim3(128, 2), 256>>>();
        softmax_finalize<<<32, 256>>>();
        writerv_kernel<<<256, 256, WRV_SMEM_BYTES>>>();
        rvreduce_kernel<<<64, 256>>>();
    }
}

// round 16
// speedup vs baseline: 2.8539x; 1.0066x over previous
#include <cuda_runtime.h>
#include <math.h>

// ---------------- problem dims ----------------
#define BB   128
#define SS   32
#define INF  512
#define HH   1024
#define OUTF 512
#define NN   16384
#define WW   128
#define CC   899
#define RVSPLIT 256
#define NHO   1028             // heads(516) + out(512) fused columns
#define NHOP  1152             // padded
#define GK    (WW + HH)        // per-step gates K = 1152
#define GZ    9                // gates split-K (chunks of 128)
#define HOZ   8                // headsout split-K (chunks of 128 over K=1024)
#define KWP   912              // padded K for Wcomb precompute (899 -> 912)

// ---------------- persistent device state / scratch ----------------
__device__ float g_mem[NN * WW];          // 8 MB
__device__ float g_h[BB * HH];
__device__ float g_c[BB * HH];
__device__ float g_rw[(size_t)BB * NN];   // 8 MB
__device__ float g_in[BB * GK];           // packed [rv | h] gates input
__device__ float g_keys[2 * BB * WW];
__device__ float g_er[BB * WW];
__device__ float g_ad[BB * WW];
__device__ float g_beta[2 * BB];
__device__ float g_gamma[2 * BB];
__device__ float g_invmem[NN];
__device__ float g_sim[(size_t)2 * BB * NN];          // 16 MB (beta-scaled sim)
__device__ float g_pmax[2 * BB * 128];
__device__ float g_psum[2 * BB * 128];
__device__ float g_mx[2 * BB];
__device__ float g_inv[2 * BB];
__device__ float g_rvpart[(size_t)RVSPLIT * BB * WW]; // 16 MB
__device__ float g_gx[(size_t)BB * SS * 4 * HH];      // 64 MB precomputed x-part of gates (+bias)
// packed / precomputed weights
__device__ float g_wg[(size_t)4 * HH * GK];           // 18.9 MB  [Wih_rv | Whh]
__device__ float g_woutT[HH * KWP];                   // 3.7 MB   Wout^T zero-padded
__device__ float g_wcomb[(size_t)NHOP * HH];          // 4.7 MB   Who_all @ Wout
__device__ float g_bcomb[NHO];
// split-K partials
__device__ float g_gpart[GZ][BB * 4 * HH];            // 18 MB
__device__ float g_hopart[HOZ][BB * NHOP];            // 4.7 MB

// ---------------- helpers ----------------
__device__ __forceinline__ float sigmoidf_(float x) { return 1.f / (1.f + __expf(-x)); }
__device__ __forceinline__ float softplusf_(float x) { return x > 20.f ? x : log1pf(__expf(x)); }

__device__ __forceinline__ void ffma2(float2 &d, float a, float2 b) {
    float2 aa = make_float2(a, a);
    asm("fma.rn.f32x2 %0, %1, %2, %0;"
        : "+l"(reinterpret_cast<unsigned long long &>(d))
        : "l"(reinterpret_cast<unsigned long long &>(aa)),
          "l"(reinterpret_cast<unsigned long long &>(b)));
}

// fetch element of the stacked head/out weight collection (row n of 1028, col c of 899)
__device__ __forceinline__ float who_fetch(
    int n, int c,
    const float *rkW, const float *wkW, const float *erW, const float *adW,
    const float *rbW, const float *rgW, const float *wbW, const float *wgW,
    const float *pW) {
    if (c >= CC) return 0.f;
    if (n < 128) return rkW[n * CC + c];
    if (n < 256) return wkW[(n - 128) * CC + c];
    if (n < 384) return erW[(n - 256) * CC + c];
    if (n < 512) return adW[(n - 384) * CC + c];
    if (n == 512) return rbW[c];
    if (n == 513) return rgW[c];
    if (n == 514) return wbW[c];
    if (n == 515) return wgW[c];
    if (n < NHO)  return (c < OUTF) ? pW[(size_t)(n - 516) * OUTF + c] : 0.f;
    return 0.f;
}

// ---------------- 128x128 tiled GEMM, 8x8/thread, reg-prefetch pipeline ----------------
template <typename FA, typename FB, typename FE>
__device__ __forceinline__ void gemm_tile128(int kb, int ke, FA fa, FB fb, FE fe) {
    __shared__ float As[16][136];
    __shared__ float Bs[16][136];
    const int tid = threadIdx.x;
    const int m0 = blockIdx.y * 128;
    const int n0 = blockIdx.x * 128;
    const int ty = tid >> 4, tx = tid & 15;
    const int lkk = tid & 15, lr0 = tid >> 4;
    float2 acc[8][4];
#pragma unroll
    for (int i = 0; i < 8; i++)
#pragma unroll
        for (int j = 0; j < 4; j++) acc[i][j] = make_float2(0.f, 0.f);

    float ra[8], rb[8];
#pragma unroll
    for (int i = 0; i < 8; i++) {
        ra[i] = fa(m0 + lr0 + 16 * i, kb + lkk);
        rb[i] = fb(n0 + lr0 + 16 * i, kb + lkk);
    }
    for (int k0 = kb; k0 < ke; k0 += 16) {
#pragma unroll
        for (int i = 0; i < 8; i++) { As[lkk][lr0 + 16 * i] = ra[i]; Bs[lkk][lr0 + 16 * i] = rb[i]; }
        __syncthreads();
        if (k0 + 16 < ke) {
#pragma unroll
            for (int i = 0; i < 8; i++) {
                ra[i] = fa(m0 + lr0 + 16 * i, k0 + 16 + lkk);
                rb[i] = fb(n0 + lr0 + 16 * i, k0 + 16 + lkk);
            }
        }
#pragma unroll
        for (int k = 0; k < 16; k++) {
            float4 a0 = *reinterpret_cast<const float4 *>(&As[k][ty * 8]);
            float4 a1 = *reinterpret_cast<const float4 *>(&As[k][ty * 8 + 4]);
            float4 b0 = *reinterpret_cast<const float4 *>(&Bs[k][tx * 8]);
            float4 b1 = *reinterpret_cast<const float4 *>(&Bs[k][tx * 8 + 4]);
            float av[8] = {a0.x, a0.y, a0.z, a0.w, a1.x, a1.y, a1.z, a1.w};
            float2 bv[4] = {make_float2(b0.x, b0.y), make_float2(b0.z, b0.w),
                            make_float2(b1.x, b1.y), make_float2(b1.z, b1.w)};
#pragma unroll
            for (int i = 0; i < 8; i++)
#pragma unroll
                for (int j = 0; j < 4; j++) ffma2(acc[i][j], av[i], bv[j]);
        }
        __syncthreads();
    }
#pragma unroll
    for (int i = 0; i < 8; i++) {
        int m = m0 + ty * 8 + i;
#pragma unroll
        for (int j = 0; j < 4; j++) {
            fe(m, n0 + tx * 8 + 2 * j, acc[i][j].x);
            fe(m, n0 + tx * 8 + 2 * j + 1, acc[i][j].y);
        }
    }
}

// ---------------- 64x64 tiled GEMM, 4x4/thread, reg-prefetch ----------------
template <typename FA, typename FB, typename FE>
__device__ __forceinline__ void gemm_tile64(int kb, int ke, FA fa, FB fb, FE fe) {
    __shared__ float As[16][72];
    __shared__ float Bs[16][72];
    const int tid = threadIdx.x;
    const int m0 = blockIdx.y * 64;
    const int n0 = blockIdx.x * 64;
    const int ty = tid >> 4, tx = tid & 15;
    const int lkk = tid & 15, lr0 = tid >> 4;
    float2 acc[4][2];
#pragma unroll
    for (int i = 0; i < 4; i++) { acc[i][0] = make_float2(0.f, 0.f); acc[i][1] = make_float2(0.f, 0.f); }

    float ra[4], rb[4];
#pragma unroll
    for (int i = 0; i < 4; i++) {
        ra[i] = fa(m0 + lr0 + 16 * i, kb + lkk);
        rb[i] = fb(n0 + lr0 + 16 * i, kb + lkk);
    }
    for (int k0 = kb; k0 < ke; k0 += 16) {
#pragma unroll
        for (int i = 0; i < 4; i++) { As[lkk][lr0 + 16 * i] = ra[i]; Bs[lkk][lr0 + 16 * i] = rb[i]; }
        __syncthreads();
        if (k0 + 16 < ke) {
#pragma unroll
            for (int i = 0; i < 4; i++) {
                ra[i] = fa(m0 + lr0 + 16 * i, k0 + 16 + lkk);
                rb[i] = fb(n0 + lr0 + 16 * i, k0 + 16 + lkk);
            }
        }
#pragma unroll
        for (int k = 0; k < 16; k++) {
            float4 a0 = *reinterpret_cast<const float4 *>(&As[k][ty * 4]);
            float4 b0 = *reinterpret_cast<const float4 *>(&Bs[k][tx * 4]);
            float av[4] = {a0.x, a0.y, a0.z, a0.w};
            float2 bv[2] = {make_float2(b0.x, b0.y), make_float2(b0.z, b0.w)};
#pragma unroll
            for (int i = 0; i < 4; i++) { ffma2(acc[i][0], av[i], bv[0]); ffma2(acc[i][1], av[i], bv[1]); }
        }
        __syncthreads();
    }
#pragma unroll
    for (int i = 0; i < 4; i++) {
        int m = m0 + ty * 4 + i;
        fe(m, n0 + tx * 4 + 0, acc[i][0].x);
        fe(m, n0 + tx * 4 + 1, acc[i][0].y);
        fe(m, n0 + tx * 4 + 2, acc[i][1].x);
        fe(m, n0 + tx * 4 + 3, acc[i][1].y);
    }
}

// ---------------- init / pack kernels ----------------
__global__ void init_kernel(const float *__restrict__ memory) {
    int i = blockIdx.x * blockDim.x + threadIdx.x;
    g_mem[i] = memory[i];                            // NN*WW == 2097152
    g_rw[i] = 1.f / NN;                              // BB*NN == 2097152
    if (i < BB * HH) { g_h[i] = 0.f; g_c[i] = 0.f; }
    if (i < BB * GK) g_in[i] = 0.f;
}

__global__ void initnorm_kernel() {
    int warp = threadIdx.x >> 5, lane = threadIdx.x & 31;
    int row = blockIdx.x * 8 + warp;
    const float *p = g_mem + (size_t)row * WW;
    float s = 0.f;
#pragma unroll
    for (int i = lane; i < WW; i += 32) { float v = p[i]; s = fmaf(v, v, s); }
#pragma unroll
    for (int o = 16; o; o >>= 1) s += __shfl_xor_sync(0xffffffffu, s, o);
    if (!lane) g_invmem[row] = 1.f / fmaxf(sqrtf(s), 1e-12f);
}

__global__ void pack_wg(const float *__restrict__ Wih, const float *__restrict__ Whh) {
    int i = blockIdx.x * blockDim.x + threadIdx.x;   // < 4096*1152
    int n = i / GK, k = i - n * GK;
    g_wg[i] = (k < WW) ? Wih[(size_t)n * (INF + WW) + INF + k]
                       : Whh[(size_t)n * HH + (k - WW)];
}

__global__ void woutT_kernel(const float *__restrict__ Wout) {
    int i = blockIdx.x * blockDim.x + threadIdx.x;   // < 1024*912
    if (i >= HH * KWP) return;
    int k = i / KWP, c = i - k * KWP;
    g_woutT[i] = (c < CC) ? Wout[(size_t)c * HH + k] : 0.f;
}

// Wcomb[m, n] = sum_c Who(m, c) * Wout(c, n)   (M=1028 pad 1152, N=1024, K=912)
__global__ void __launch_bounds__(256, 2) wcomb_gemm(
    const float *__restrict__ rkW, const float *__restrict__ wkW,
    const float *__restrict__ erW, const float *__restrict__ adW,
    const float *__restrict__ rbW, const float *__restrict__ rgW,
    const float *__restrict__ wbW, const float *__restrict__ wgW,
    const float *__restrict__ pW) {
    auto fa = [&](int m, int c) { return who_fetch(m, c, rkW, wkW, erW, adW, rbW, rgW, wbW, wgW, pW); };
    auto fb = [&](int n, int c) { return g_woutT[n * KWP + c]; };
    auto fe = [&](int m, int n, float v) { g_wcomb[(size_t)m * HH + n] = v; };
    gemm_tile128(0, KWP, fa, fb, fe);
}

__global__ void bcomb_kernel(
    const float *__restrict__ rkW, const float *__restrict__ wkW,
    const float *__restrict__ erW, const float *__restrict__ adW,
    const float *__restrict__ rbW, const float *__restrict__ rgW,
    const float *__restrict__ wbW, const float *__restrict__ wgW,
    const float *__restrict__ pW, const float *__restrict__ bout,
    const float *__restrict__ rkb, const float *__restrict__ rbb, const float *__restrict__ rgb,
    const float *__restrict__ wkb, const float *__restrict__ wbb, const float *__restrict__ wgb,
    const float *__restrict__ erb, const float *__restrict__ adb, const float *__restrict__ pb) {
    int n = blockIdx.x * blockDim.x + threadIdx.x;
    if (n >= NHO) return;
    float s = 0.f;
    for (int c = 0; c < CC; c++) s += who_fetch(n, c, rkW, wkW, erW, adW, rbW, rgW, wbW, wgW, pW) * bout[c];
    float bias;
    if (n < 128)       bias = rkb[n];
    else if (n < 256)  bias = wkb[n - 128];
    else if (n < 384)  bias = erb[n - 256];
    else if (n < 512)  bias = adb[n - 384];
    else if (n == 512) bias = rbb[0];
    else if (n == 513) bias = rgb[0];
    else if (n == 514) bias = wbb[0];
    else if (n == 515) bias = wgb[0];
    else               bias = pb[n - 516];
    g_bcomb[n] = s + bias;
}

// one-time: gx[(b*S+t), n] = x @ Wih_x^T + bih + bhh   (M=4096, N=4096, K=512)
__global__ void __launch_bounds__(256, 2) xgemm(
    const float *__restrict__ x, const float *__restrict__ Wih,
    const float *__restrict__ bih, const float *__restrict__ bhh) {
    auto fa = [&](int m, int k) { return x[(size_t)m * INF + k]; };
    auto fb = [&](int n, int k) { return Wih[(size_t)n * (INF + WW) + k]; };
    auto fe = [&](int m, int n, float v) { g_gx[(size_t)m * 4 * HH + n] = v + bih[n] + bhh[n]; };
    gemm_tile128(0, INF, fa, fb, fe);
}

// ---------------- per-step kernels ----------------
// gates partials: g_in @ g_wg^T   (M=128, N=4096, K=1152 split GZ x 128)
__global__ void __launch_bounds__(256, 2) gates_gemm() {
    const int z = blockIdx.z;
    auto fa = [&](int m, int k) { return g_in[m * GK + k]; };
    auto fb = [&](int n, int k) { return g_wg[(size_t)n * GK + k]; };
    auto fe = [&](int m, int n, float v) { g_gpart[z][m * 4 * HH + n] = v; };
    gemm_tile128(z * 128, (z + 1) * 128, fa, fb, fe);
}

__global__ void lstm_kernel(int t) {
    int idx = blockIdx.x * blockDim.x + threadIdx.x;   // 0..32767
    int b = idx >> 8;
    int j4 = (idx & 255) * 4;
    size_t gxbase = ((size_t)(b * SS + t)) * 4 * HH;
    int pbase = b * 4 * HH;
    float4 gi = *reinterpret_cast<const float4 *>(&g_gx[gxbase + j4]);
    float4 gf = *reinterpret_cast<const float4 *>(&g_gx[gxbase + HH + j4]);
    float4 gg = *reinterpret_cast<const float4 *>(&g_gx[gxbase + 2 * HH + j4]);
    float4 go = *reinterpret_cast<const float4 *>(&g_gx[gxbase + 3 * HH + j4]);
#pragma unroll
    for (int z = 0; z < GZ; z++) {
        float4 a = *reinterpret_cast<const float4 *>(&g_gpart[z][pbase + j4]);
        float4 bq = *reinterpret_cast<const float4 *>(&g_gpart[z][pbase + HH + j4]);
        float4 cq = *reinterpret_cast<const float4 *>(&g_gpart[z][pbase + 2 * HH + j4]);
        float4 d = *reinterpret_cast<const float4 *>(&g_gpart[z][pbase + 3 * HH + j4]);
        gi.x += a.x; gi.y += a.y; gi.z += a.z; gi.w += a.w;
        gf.x += bq.x; gf.y += bq.y; gf.z += bq.z; gf.w += bq.w;
        gg.x += cq.x; gg.y += cq.y; gg.z += cq.z; gg.w += cq.w;
        go.x += d.x; go.y += d.y; go.z += d.z; go.w += d.w;
    }
    float4 c = *reinterpret_cast<const float4 *>(&g_c[b * HH + j4]);
    float4 nc, nh;
    nc.x = sigmoidf_(gf.x) * c.x + sigmoidf_(gi.x) * tanhf(gg.x);
    nc.y = sigmoidf_(gf.y) * c.y + sigmoidf_(gi.y) * tanhf(gg.y);
    nc.z = sigmoidf_(gf.z) * c.z + sigmoidf_(gi.z) * tanhf(gg.z);
    nc.w = sigmoidf_(gf.w) * c.w + sigmoidf_(gi.w) * tanhf(gg.w);
    nh.x = sigmoidf_(go.x) * tanhf(nc.x);
    nh.y = sigmoidf_(go.y) * tanhf(nc.y);
    nh.z = sigmoidf_(go.z) * tanhf(nc.z);
    nh.w = sigmoidf_(go.w) * tanhf(nc.w);
    *reinterpret_cast<float4 *>(&g_c[b * HH + j4]) = nc;
    *reinterpret_cast<float4 *>(&g_h[b * HH + j4]) = nh;
    *reinterpret_cast<float4 *>(&g_in[b * GK + WW + j4]) = nh;
}

// fused heads+out partials directly from h: h @ Wcomb^T (M=128, N=1028 pad, K=1024 split HOZ x 128)
__global__ void __launch_bounds__(256, 4) headsout_gemm() {
    const int z = blockIdx.z;
    auto fa = [&](int m, int k) { return g_h[m * HH + k]; };
    auto fb = [&](int n, int k) { return g_wcomb[(size_t)n * HH + k]; };
    auto fe = [&](int m, int n, float v) { g_hopart[z][m * NHOP + n] = v; };
    gemm_tile64(z * 128, (z + 1) * 128, fa, fb, fe);
}

// reduce HOZ partials + combined bias + activations; writes output for step t
__global__ void headsout_epi(float *__restrict__ out, int t) {
    int i = blockIdx.x * blockDim.x + threadIdx.x;   // 0 .. 128*1028-1
    int b = i / NHO, n = i - b * NHO;
    float v = g_bcomb[n];
#pragma unroll
    for (int z = 0; z < HOZ; z++) v += g_hopart[z][b * NHOP + n];
    if (n < 128)      g_keys[b * WW + n] = v;
    else if (n < 256) g_keys[(128 + b) * WW + (n - 128)] = v;
    else if (n < 384) g_er[b * WW + (n - 256)] = sigmoidf_(v);
    else if (n < 512) g_ad[b * WW + (n - 384)] = tanhf(v);
    else if (n == 512) g_beta[b] = softplusf_(v);
    else if (n == 513) g_gamma[b] = 1.f + softplusf_(v);
    else if (n == 514) g_beta[128 + b] = softplusf_(v);
    else if (n == 515) g_gamma[128 + b] = 1.f + softplusf_(v);
    else { int o = n - 516; out[(size_t)b * SS * OUTF + (size_t)t * OUTF + o] = v; }
}

// s[r,n] = beta[r]*(key_r . mem_n)*invkey[r]*invmem[n]; writes s + per-block softmax partials
__global__ void __launch_bounds__(256, 2) sim_gemm() {
    __shared__ float As[16][136];
    __shared__ float Bs[16][136];
    __shared__ float sh_bik[128];
    const int tid = threadIdx.x;
    const int r0 = blockIdx.y * 128;
    const int n0 = blockIdx.x * 128;
    const int nblk = blockIdx.x;
    const int ty = tid >> 4, tx = tid & 15;
    const int lkk = tid & 15, lr0 = tid >> 4;
    {
        int row = tid >> 1, part = tid & 1;
        const float *p = g_keys + (r0 + row) * WW;
        float s = 0.f;
#pragma unroll
        for (int j = 0; j < 64; j++) { float v = p[part + 2 * j]; s = fmaf(v, v, s); }
        s += __shfl_xor_sync(0xffffffffu, s, 1);
        if (!part) sh_bik[row] = g_beta[r0 + row] / fmaxf(sqrtf(s), 1e-12f);
    }
    float2 acc[8][4];
#pragma unroll
    for (int i = 0; i < 8; i++)
#pragma unroll
        for (int j = 0; j < 4; j++) acc[i][j] = make_float2(0.f, 0.f);

    float ra[8], rb[8];
#pragma unroll
    for (int i = 0; i < 8; i++) {
        ra[i] = g_keys[(r0 + lr0 + 16 * i) * WW + lkk];
        rb[i] = g_mem[(size_t)(n0 + lr0 + 16 * i) * WW + lkk];
    }
    for (int k0 = 0; k0 < WW; k0 += 16) {
#pragma unroll
        for (int i = 0; i < 8; i++) { As[lkk][lr0 + 16 * i] = ra[i]; Bs[lkk][lr0 + 16 * i] = rb[i]; }
        __syncthreads();
        if (k0 + 16 < WW) {
#pragma unroll
            for (int i = 0; i < 8; i++) {
                ra[i] = g_keys[(r0 + lr0 + 16 * i) * WW + k0 + 16 + lkk];
                rb[i] = g_mem[(size_t)(n0 + lr0 + 16 * i) * WW + k0 + 16 + lkk];
            }
        }
#pragma unroll
        for (int k = 0; k < 16; k++) {
            float4 a0 = *reinterpret_cast<const float4 *>(&As[k][ty * 8]);
            float4 a1 = *reinterpret_cast<const float4 *>(&As[k][ty * 8 + 4]);
            float4 b0 = *reinterpret_cast<const float4 *>(&Bs[k][tx * 8]);
            float4 b1 = *reinterpret_cast<const float4 *>(&Bs[k][tx * 8 + 4]);
            float av[8] = {a0.x, a0.y, a0.z, a0.w, a1.x, a1.y, a1.z, a1.w};
            float2 bv[4] = {make_float2(b0.x, b0.y), make_float2(b0.z, b0.w),
                            make_float2(b1.x, b1.y), make_float2(b1.z, b1.w)};
#pragma unroll
            for (int i = 0; i < 8; i++)
#pragma unroll
                for (int j = 0; j < 4; j++) ffma2(acc[i][j], av[i], bv[j]);
        }
        __syncthreads();
    }
    float im[8];
#pragma unroll
    for (int c = 0; c < 8; c++) im[c] = g_invmem[n0 + tx * 8 + c];
#pragma unroll
    for (int i = 0; i < 8; i++) {
        int rloc = ty * 8 + i;
        float bik = sh_bik[rloc];
        float vals[8];
#pragma unroll
        for (int j = 0; j < 4; j++) {
            vals[2 * j]     = acc[i][j].x * bik * im[2 * j];
            vals[2 * j + 1] = acc[i][j].y * bik * im[2 * j + 1];
        }
        float *dst = g_sim + (size_t)(r0 + rloc) * NN + n0 + tx * 8;
        *reinterpret_cast<float4 *>(dst)     = make_float4(vals[0], vals[1], vals[2], vals[3]);
        *reinterpret_cast<float4 *>(dst + 4) = make_float4(vals[4], vals[5], vals[6], vals[7]);
        float m = -1e30f;
#pragma unroll
        for (int c = 0; c < 8; c++) m = fmaxf(m, vals[c]);
        float s = 0.f;
#pragma unroll
        for (int c = 0; c < 8; c++) s += __expf(vals[c] - m);
#pragma unroll
        for (int off = 1; off < 16; off <<= 1) {
            float om = __shfl_xor_sync(0xffffffffu, m, off);
            float os = __shfl_xor_sync(0xffffffffu, s, off);
            float nm = fmaxf(m, om);
            s = s * __expf(m - nm) + os * __expf(om - nm);
            m = nm;
        }
        if (tx == 0) {
            int r = r0 + rloc;
            g_pmax[r * 128 + nblk] = m;
            g_psum[r * 128 + nblk] = s;
        }
    }
}

__global__ void softmax_finalize() {
    int r = blockIdx.x * 8 + (threadIdx.x >> 5);
    int lane = threadIdx.x & 31;
    float m = -1e30f, s = 0.f;
    for (int k = lane; k < 128; k += 32) {
        float pm = g_pmax[r * 128 + k], ps = g_psum[r * 128 + k];
        float nm = fmaxf(m, pm);
        s = s * __expf(m - nm) + ps * __expf(pm - nm);
        m = nm;
    }
#pragma unroll
    for (int off = 16; off; off >>= 1) {
        float om = __shfl_xor_sync(0xffffffffu, m, off);
        float os = __shfl_xor_sync(0xffffffffu, s, off);
        float nm = fmaxf(m, om);
        s = s * __expf(m - nm) + os * __expf(om - nm);
        m = nm;
    }
    if (!lane) { g_mx[r] = m; g_inv[r] = 1.f / s; }
}

// -------- fused memory write + rv partial over a 64-row n-chunk --------
#define SM_RWS   0
#define SM_ERS   2176
#define SM_ADS   6528
#define SM_MEMU  8704
#define SM_CONST 17152
#define WRV_SMEM_BYTES (17920 * 4)

__global__ void __launch_bounds__(256) writerv_kernel() {
    extern __shared__ float sm[];
    float *wws = sm;                 // [32][68]
    float *ers = sm + SM_ERS;        // [32][136]
    float *ads = sm + SM_ADS;        // [32][136]
    float *rws = sm + SM_RWS;        // [64][136]
    float *memu = sm + SM_MEMU;      // [64][132]
    float *f1w = sm + SM_CONST, *f2w = f1w + 128, *mxw = f2w + 128;
    float *f1r = mxw + 128, *f2r = f1r + 128, *mxr = f2r + 128;

    int tid = threadIdx.x;
    if (tid < 128) {
        float gw = g_gamma[128 + tid];
        f1w[tid] = gw * g_inv[128 + tid];
        f2w[tid] = (1.f - gw) / NN;
        mxw[tid] = g_mx[128 + tid];
        float gr = g_gamma[tid];
        f1r[tid] = gr * g_inv[tid];
        f2r[tid] = 1.f - gr;
        mxr[tid] = g_mx[tid];
    }
    __syncthreads();

    const int n0 = blockIdx.x * 64;
    const int nl0 = (tid >> 4) * 4;
    const int tx = tid & 15;
    const int w0 = tx * 8;

    float2 eacc[4][4]; float2 aacc[4][4];
#pragma unroll
    for (int i = 0; i < 4; i++)
#pragma unroll
        for (int j = 0; j < 4; j++) { eacc[i][j] = make_float2(0.f, 0.f); aacc[i][j] = make_float2(0.f, 0.f); }

    for (int bt = 0; bt < BB; bt += 32) {
#pragma unroll
        for (int i = 0; i < 8; i++) {
            int idx = tid + i * 256;
            int bl = idx >> 6, nl = idx & 63;
            int b = bt + bl;
            float sv = g_sim[(size_t)(128 + b) * NN + n0 + nl];
            wws[bl * 68 + nl] = f1w[b] * __expf(sv - mxw[b]) + f2w[b];
        }
#pragma unroll
        for (int i = 0; i < 16; i++) {
            int idx = tid + i * 256;
            int bl = idx >> 7, w = idx & 127;
            ers[bl * 136 + w] = g_er[(bt + bl) * WW + w];
            ads[bl * 136 + w] = g_ad[(bt + bl) * WW + w];
        }
        __syncthreads();
#pragma unroll 4
        for (int bl = 0; bl < 32; bl++) {
            float wv[4];
#pragma unroll
            for (int i = 0; i < 4; i++) wv[i] = wws[bl * 68 + nl0 + i];
            float4 e0 = *reinterpret_cast<const float4 *>(&ers[bl * 136 + w0]);
            float4 e1 = *reinterpret_cast<const float4 *>(&ers[bl * 136 + w0 + 4]);
            float4 d0 = *reinterpret_cast<const float4 *>(&ads[bl * 136 + w0]);
            float4 d1 = *reinterpret_cast<const float4 *>(&ads[bl * 136 + w0 + 4]);
            float2 ev[4] = {make_float2(e0.x, e0.y), make_float2(e0.z, e0.w),
                            make_float2(e1.x, e1.y), make_float2(e1.z, e1.w)};
            float2 av[4] = {make_float2(d0.x, d0.y), make_float2(d0.z, d0.w),
                            make_float2(d1.x, d1.y), make_float2(d1.z, d1.w)};
#pragma unroll
            for (int i = 0; i < 4; i++)
#pragma unroll
                for (int j = 0; j < 4; j++) { ffma2(eacc[i][j], wv[i], ev[j]); ffma2(aacc[i][j], wv[i], av[j]); }
        }
        __syncthreads();
    }

#pragma unroll
    for (int i = 0; i < 4; i++) {
        int nl = nl0 + i;
        size_t base = (size_t)(n0 + nl) * WW + w0;
        float ss = 0.f;
#pragma unroll
        for (int j = 0; j < 4; j++) {
            float m0v = g_mem[base + 2 * j], m1v = g_mem[base + 2 * j + 1];
            float a0 = m0v * (1.f - eacc[i][j].x) + aacc[i][j].x;
            float a1 = m1v * (1.f - eacc[i][j].y) + aacc[i][j].y;
            g_mem[base + 2 * j]     = a0;
            g_mem[base + 2 * j + 1] = a1;
            memu[nl * 132 + w0 + 2 * j]     = a0;
            memu[nl * 132 + w0 + 2 * j + 1] = a1;
            ss = fmaf(a0, a0, fmaf(a1, a1, ss));
        }
#pragma unroll
        for (int o = 1; o < 16; o <<= 1) ss += __shfl_xor_sync(0xffffffffu, ss, o);
        if (!tx) g_invmem[n0 + nl] = 1.f / fmaxf(sqrtf(ss), 1e-12f);
    }
#pragma unroll
    for (int i = 0; i < 32; i++) {
        int idx = tid + i * 256;
        int b = idx >> 6, nl = idx & 63;
        size_t off = (size_t)b * NN + n0 + nl;
        float sv = g_sim[off];
        float w = f1r[b] * __expf(sv - mxr[b]) + f2r[b] * g_rw[off];
        g_rw[off] = w;
        rws[nl * 136 + b] = w;
    }
    __syncthreads();

    int b0 = (tid >> 4) * 8, wq0 = (tid & 15) * 8;
    float2 acc[8][4];
#pragma unroll
    for (int i = 0; i < 8; i++)
#pragma unroll
        for (int j = 0; j < 4; j++) acc[i][j] = make_float2(0.f, 0.f);

    for (int nl = 0; nl < 64; nl++) {
        float4 v0 = *reinterpret_cast<const float4 *>(&memu[nl * 132 + wq0]);
        float4 v1 = *reinterpret_cast<const float4 *>(&memu[nl * 132 + wq0 + 4]);
        float2 mv[4] = {make_float2(v0.x, v0.y), make_float2(v0.z, v0.w),
                        make_float2(v1.x, v1.y), make_float2(v1.z, v1.w)};
        float4 r0 = *reinterpret_cast<const float4 *>(&rws[nl * 136 + b0]);
        float4 r1 = *reinterpret_cast<const float4 *>(&rws[nl * 136 + b0 + 4]);
        float rvv[8] = {r0.x, r0.y, r0.z, r0.w, r1.x, r1.y, r1.z, r1.w};
#pragma unroll
        for (int i = 0; i < 8; i++)
#pragma unroll
            for (int j = 0; j < 4; j++) ffma2(acc[i][j], rvv[i], mv[j]);
    }
    float *dst = g_rvpart + (size_t)blockIdx.x * BB * WW;
#pragma unroll
    for (int i = 0; i < 8; i++)
#pragma unroll
        for (int j = 0; j < 4; j++) {
            dst[(b0 + i) * WW + wq0 + 2 * j]     = acc[i][j].x;
            dst[(b0 + i) * WW + wq0 + 2 * j + 1] = acc[i][j].y;
        }
}

// reduce rv partials directly into the packed gates input (cols 0..127)
__global__ void rvreduce_kernel() {
    int o = blockIdx.x * blockDim.x + threadIdx.x;
    if (o >= BB * WW) return;
    float s = 0.f;
    for (int ch = 0; ch < RVSPLIT; ch++) s += g_rvpart[(size_t)ch * BB * WW + o];
    int b = o >> 7, w = o & 127;
    g_in[b * GK + w] = s;
}

// ---------------- launch ----------------
extern "C" void kernel_launch(void *const *d_in, const int *in_sizes, int n_in,
                              void *d_out, int out_size) {
    const float *x      = (const float *)d_in[0];
    const float *memory = (const float *)d_in[1];
    const float *Wih    = (const float *)d_in[2];
    const float *Whh    = (const float *)d_in[3];
    const float *bih    = (const float *)d_in[4];
    const float *bhh    = (const float *)d_in[5];
    const float *Wout   = (const float *)d_in[6];
    const float *bout   = (const float *)d_in[7];
    const float *rkW    = (const float *)d_in[8];
    const float *rkb    = (const float *)d_in[9];
    const float *rbW    = (const float *)d_in[10];
    const float *rbb    = (const float *)d_in[11];
    const float *rgW    = (const float *)d_in[12];
    const float *rgb    = (const float *)d_in[13];
    const float *wkW    = (const float *)d_in[14];
    const float *wkb    = (const float *)d_in[15];
    const float *wbW    = (const float *)d_in[16];
    const float *wbb    = (const float *)d_in[17];
    const float *wgW    = (const float *)d_in[18];
    const float *wgb    = (const float *)d_in[19];
    const float *erW    = (const float *)d_in[20];
    const float *erb    = (const float *)d_in[21];
    const float *adW    = (const float *)d_in[22];
    const float *adb    = (const float *)d_in[23];
    const float *pW     = (const float *)d_in[24];
    const float *pb     = (const float *)d_in[25];
    float *out = (float *)d_out;

    cudaFuncSetAttribute(writerv_kernel, cudaFuncAttributeMaxDynamicSharedMemorySize, WRV_SMEM_BYTES);

    init_kernel<<<8192, 256>>>(memory);
    initnorm_kernel<<<NN / 8, 256>>>();
    pack_wg<<<(4 * HH * GK) / 256, 256>>>(Wih, Whh);
    woutT_kernel<<<(HH * KWP + 255) / 256, 256>>>(Wout);
    wcomb_gemm<<<dim3(8, 9), 256>>>(rkW, wkW, erW, adW, rbW, rgW, wbW, wgW, pW);
    bcomb_kernel<<<(NHO + 255) / 256, 256>>>(rkW, wkW, erW, adW, rbW, rgW, wbW, wgW, pW, bout,
                                             rkb, rbb, rgb, wkb, wbb, wgb, erb, adb, pb);
    xgemm<<<dim3(32, 32), 256>>>(x, Wih, bih, bhh);
    for (int t = 0; t < SS; t++) {
        gates_gemm<<<dim3(32, 1, GZ), 256>>>();
        lstm_kernel<<<128, 256>>>(t);
        headsout_gemm<<<dim3(17, 2, HOZ), 256>>>();
        headsout_epi<<<514, 256>>>(out, t);
        sim_gemm<<<dim3(128, 2), 256>>>();
        softmax_finalize<<<32, 256>>>();
        writerv_kernel<<<256, 256, WRV_SMEM_BYTES>>>();
        rvreduce_kernel<<<64, 256>>>();
    }
}